// round 13
// baseline (speedup 1.0000x reference)
#include <cuda_runtime.h>
#include <cuda_bf16.h>
#include <cstdint>
#include <cstddef>

// ---------------- problem constants ----------------
#define BATCH  256
#define DMODEL 512
#define DA     256
#define DB     256
#define RR     8
#define NP     2048
#define DP     4608
#define SA     4
#define DKK    64
#define HIDN   1024
#define NDE    65536           // DB*DA
#define KEXP   13824           // 3*DP (hi | lo | hi)
#define KZ     4               // keys split-K
#define KZLEN  (KEXP / KZ)     // 3456
#define BDS    8               // b_delta split-K
#define BDK    (NP / BDS)      // 256

// output layout (flattened tuple: output, alpha, W_assembled, keys)
#define OUT_ALPHA  (BATCH*DMODEL)
#define OUT_W      (OUT_ALPHA + BATCH*NP)
#define OUT_KEYS   (OUT_W + (size_t)BATCH*DB*DA)

// ---------------- scratch (device globals; no allocation allowed) ----------------
__device__ float g_hid [BATCH*HIDN];
__device__ float g_hA  [BATCH*DA];
__device__ float g_qw  [BATCH*SA*DKK];
__device__ float g_kn  [NP*SA*DKK];
__device__ float g_bt  [BDS*BATCH*DB];                  // b_delta split-K partials (2MB)
__device__ float g_hmid[BATCH*DA];
__device__ float g_hid2[BATCH*HIDN];
__device__ float g_kp  [KZ*NP*SA*DKK];                  // keys split-K partials
__device__ __nv_bfloat16 g_alphab[BATCH*NP];            // alpha in bf16
__device__ __nv_bfloat16 g_UVb[(size_t)NP*NDE];         // UV in bf16 (268MB)
__device__ __nv_bfloat16 g_poolx[(size_t)NP*KEXP];      // pool hi/lo expanded (56.6MB)
__device__ __nv_bfloat16 g_wkx[(size_t)KEXP*256];       // W_K hi/lo expanded (7MB)

// ---------------- helpers ----------------
__device__ __forceinline__ float gelu_f(float x) {
    const float c = 0.7978845608028654f;
    return 0.5f * x * (1.0f + tanhf(c * (x + 0.044715f * x * x * x)));
}
__device__ __forceinline__ uint32_t smem_u32(const void* p) {
    uint32_t a;
    asm("{ .reg .u64 t; cvta.to.shared.u64 t, %1; cvt.u32.u64 %0, t; }" : "=r"(a) : "l"(p));
    return a;
}
__device__ __forceinline__ void ldmat_x4(uint32_t& r0, uint32_t& r1, uint32_t& r2, uint32_t& r3,
                                         uint32_t addr) {
    asm volatile("ldmatrix.sync.aligned.m8n8.x4.shared.b16 {%0,%1,%2,%3}, [%4];"
                 : "=r"(r0), "=r"(r1), "=r"(r2), "=r"(r3) : "r"(addr));
}
__device__ __forceinline__ void ldmat_x4_t(uint32_t& r0, uint32_t& r1, uint32_t& r2, uint32_t& r3,
                                           uint32_t addr) {
    asm volatile("ldmatrix.sync.aligned.m8n8.x4.trans.shared.b16 {%0,%1,%2,%3}, [%4];"
                 : "=r"(r0), "=r"(r1), "=r"(r2), "=r"(r3) : "r"(addr));
}
__device__ __forceinline__ void mma_bf16(float* d, const uint32_t* a, const uint32_t* b) {
    asm volatile("mma.sync.aligned.m16n8k16.row.col.f32.bf16.bf16.f32 "
                 "{%0,%1,%2,%3}, {%4,%5,%6,%7}, {%8,%9}, {%0,%1,%2,%3};"
                 : "+f"(d[0]), "+f"(d[1]), "+f"(d[2]), "+f"(d[3])
                 : "r"(a[0]), "r"(a[1]), "r"(a[2]), "r"(a[3]), "r"(b[0]), "r"(b[1]));
}
__device__ __forceinline__ void cpa16(uint32_t dst, const void* src) {
    asm volatile("cp.async.cg.shared.global [%0], [%1], 16;" :: "r"(dst), "l"(src));
}
#define CP_COMMIT() asm volatile("cp.async.commit_group;" ::: "memory")
#define CP_WAIT1()  asm volatile("cp.async.wait_group 1;" ::: "memory")
#define CP_WAIT2()  asm volatile("cp.async.wait_group 2;" ::: "memory")

// ---------------- generic 64x64x16 SGEMM (small MLPs) ----------------
template <int ACT>
__global__ void gemm64(const float* __restrict__ A, const float* __restrict__ B,
                       const float* __restrict__ bias, float* __restrict__ C,
                       int K, int lda, int ldb, int ldc)
{
    __shared__ float As[16][64];
    __shared__ float Bs[16][64];
    int tid = threadIdx.x;
    int m0 = blockIdx.y * 64, n0 = blockIdx.x * 64;
    int am = tid >> 2, ak = (tid & 3) * 4;
    int bk = tid >> 4, bn = (tid & 15) * 4;
    int ty = tid >> 4, tx = tid & 15;
    float acc[4][4] = {};
    const float* Ap = A + (size_t)(m0 + am) * lda + ak;
    const float* Bp = B + (size_t)bk * ldb + n0 + bn;
    float4 av = *(const float4*)Ap;
    float4 bv = *(const float4*)Bp;
    for (int k0 = 0; k0 < K; k0 += 16) {
        As[ak + 0][am] = av.x; As[ak + 1][am] = av.y; As[ak + 2][am] = av.z; As[ak + 3][am] = av.w;
        *(float4*)&Bs[bk][bn] = bv;
        __syncthreads();
        if (k0 + 16 < K) {
            av = *(const float4*)(Ap + (k0 + 16));
            bv = *(const float4*)(Bp + (size_t)(k0 + 16) * ldb);
        }
#pragma unroll
        for (int kk = 0; kk < 16; kk++) {
            float ar[4], br[4];
            *(float4*)ar = *(const float4*)&As[kk][ty * 4];
            *(float4*)br = *(const float4*)&Bs[kk][tx * 4];
#pragma unroll
            for (int i = 0; i < 4; i++)
#pragma unroll
                for (int j = 0; j < 4; j++) acc[i][j] += ar[i] * br[j];
        }
        __syncthreads();
    }
#pragma unroll
    for (int i = 0; i < 4; i++) {
        int m = m0 + ty * 4 + i;
#pragma unroll
        for (int j = 0; j < 4; j++) {
            int n = n0 + tx * 4 + j;
            float c = acc[i][j];
            if (bias) c += bias[n];
            if (ACT == 1) c = gelu_f(c);
            C[(size_t)m * ldc + n] = c;
        }
    }
}

// ---------------- b_delta split-K: partial[z] = alpha[:,kz] @ bias[kz,:] ----------------
__global__ void bdelta_kernel(const float* __restrict__ alpha, const float* __restrict__ pool,
                              float* __restrict__ bt)
{
    __shared__ float As[16][64];
    __shared__ float Bs[16][64];
    int tid = threadIdx.x;
    int m0 = blockIdx.y * 64, n0 = blockIdx.x * 64;
    int z = blockIdx.z;
    int kbeg = z * BDK;
    int am = tid >> 2, ak = (tid & 3) * 4;
    int bk = tid >> 4, bn = (tid & 15) * 4;
    int ty = tid >> 4, tx = tid & 15;
    float acc[4][4] = {};
    const float* Ap = alpha + (size_t)(m0 + am) * NP + kbeg + ak;
    const float* Bp = pool + 4096 + (size_t)(kbeg + bk) * DP + n0 + bn;
    float4 av = *(const float4*)Ap;
    float4 bv = *(const float4*)Bp;
    for (int k0 = 0; k0 < BDK; k0 += 16) {
        As[ak + 0][am] = av.x; As[ak + 1][am] = av.y; As[ak + 2][am] = av.z; As[ak + 3][am] = av.w;
        *(float4*)&Bs[bk][bn] = bv;
        __syncthreads();
        if (k0 + 16 < BDK) {
            av = *(const float4*)(Ap + (k0 + 16));
            bv = *(const float4*)(Bp + (size_t)(k0 + 16) * DP);
        }
#pragma unroll
        for (int kk = 0; kk < 16; kk++) {
            float ar[4], br[4];
            *(float4*)ar = *(const float4*)&As[kk][ty * 4];
            *(float4*)br = *(const float4*)&Bs[kk][tx * 4];
#pragma unroll
            for (int i = 0; i < 4; i++)
#pragma unroll
                for (int j = 0; j < 4; j++) acc[i][j] += ar[i] * br[j];
        }
        __syncthreads();
    }
    float* outp = bt + (size_t)z * BATCH * DB;
#pragma unroll
    for (int i = 0; i < 4; i++)
#pragma unroll
        for (int j = 0; j < 4; j++)
            outp[(size_t)(m0 + ty * 4 + i) * DB + n0 + tx * 4 + j] = acc[i][j];
}

// ---------------- hi/lo expansion: pool -> poolx [n][hi|lo|hi] ----------------
__global__ void expand_pool_kernel(const float* __restrict__ pool, __nv_bfloat16* __restrict__ px)
{
    int n = blockIdx.x, tid = threadIdx.x;
    const float* src = pool + (size_t)n * DP;
    __nv_bfloat16* dst = px + (size_t)n * KEXP;
#pragma unroll 2
    for (int p = tid; p < DP; p += 256) {
        float x = src[p];
        __nv_bfloat16 hi = __float2bfloat16(x);
        __nv_bfloat16 lo = __float2bfloat16(x - __bfloat162float(hi));
        dst[p] = hi;
        dst[DP + p] = lo;
        dst[2 * DP + p] = hi;
    }
}

// ---------------- hi/lo expansion: W_K -> wkx [k][c], c=a*64+q ----------------
__global__ void expand_wk_kernel(const float* __restrict__ WK, __nv_bfloat16* __restrict__ wx)
{
    int k = blockIdx.x, c = threadIdx.x;   // 13824 blocks x 256 threads
    int s = k / DP, p = k % DP;
    int a = c >> 6, q = c & 63;
    float x = WK[(size_t)a * DP * DKK + (size_t)p * DKK + q];
    __nv_bfloat16 hi = __float2bfloat16(x);
    __nv_bfloat16 v;
    if (s < 2) v = hi;
    else v = __float2bfloat16(x - __bfloat162float(hi));
    wx[(size_t)k * 256 + c] = v;
}

// ---------------- keys mma v3: 4-stage cp.async ring, 1 barrier/chunk ----------------
// BM=64, BN=64, BK=32, 128 threads (2m x 2n warps), KZ=4 split-K.
#define K_ABY (64 * 80)     // 5120 B
#define K_BBY (32 * 144)    // 4608 B
#define K_STG (K_ABY + K_BBY)

__global__ void __launch_bounds__(128, 4) keys_mma_kernel(
    const __nv_bfloat16* __restrict__ Ax, const __nv_bfloat16* __restrict__ Bx,
    float* __restrict__ kp)
{
    __shared__ __align__(16) char smem[4 * K_STG];   // 38912 B
    int tid = threadIdx.x, lane = tid & 31, wid = tid >> 5;
    int warp_m = wid & 1, warp_n = wid >> 1;
    int n0 = blockIdx.x * 64;
    int m0 = blockIdx.y * 64;
    int z  = blockIdx.z;
    int kbase = z * KZLEN;

    uint32_t sbase = smem_u32(smem);
    int ar = tid >> 2, aseg = tid & 3;
    int br = tid >> 3, bseg = tid & 7;
    const __nv_bfloat16* Agb = Ax + (size_t)m0 * KEXP + kbase;
    const __nv_bfloat16* Bgb = Bx + (size_t)kbase * 256 + n0;

    float acc[2][4][4];
#pragma unroll
    for (int i = 0; i < 2; i++)
#pragma unroll
        for (int j = 0; j < 4; j++)
#pragma unroll
            for (int q = 0; q < 4; q++) acc[i][j][q] = 0.0f;

    const int NC = KZLEN / 32;   // 108
#define K_ISSUE(cc, ss) do { \
    uint32_t ab = sbase + (ss) * K_STG, bbf = ab + K_ABY; \
    cpa16(ab + (uint32_t)ar * 80 + aseg * 16, Agb + (size_t)ar * KEXP + (cc) * 32 + aseg * 8); \
    cpa16(ab + (uint32_t)(ar + 32) * 80 + aseg * 16, Agb + (size_t)(ar + 32) * KEXP + (cc) * 32 + aseg * 8); \
    cpa16(bbf + (uint32_t)br * 144 + bseg * 16, Bgb + (size_t)((cc) * 32 + br) * 256 + bseg * 8); \
    cpa16(bbf + (uint32_t)(br + 16) * 144 + bseg * 16, Bgb + (size_t)((cc) * 32 + br + 16) * 256 + bseg * 8); \
} while (0)

    K_ISSUE(0, 0); CP_COMMIT();
    K_ISSUE(1, 1); CP_COMMIT();
    K_ISSUE(2, 2); CP_COMMIT();

    uint32_t a_lm = (uint32_t)(warp_m * 32 + (lane & 15)) * 80 + (lane >> 4) * 16;
    uint32_t b_k = (uint32_t)(lane & 15) * 144;
    uint32_t b_c = (uint32_t)(warp_n * 32 + (lane >> 4) * 8) * 2;

    for (int c = 0; c < NC; c++) {
        CP_WAIT2();
        __syncthreads();
        if (c + 3 < NC) K_ISSUE(c + 3, (c + 3) & 3);
        CP_COMMIT();
        uint32_t ab = sbase + (c & 3) * K_STG, bbf = ab + K_ABY;
#pragma unroll
        for (int k16 = 0; k16 < 2; k16++) {
            uint32_t af[2][4];
            uint32_t bf[4][2];
#pragma unroll
            for (int mt = 0; mt < 2; mt++)
                ldmat_x4(af[mt][0], af[mt][1], af[mt][2], af[mt][3],
                         ab + a_lm + mt * 16 * 80 + k16 * 32);
#pragma unroll
            for (int bt = 0; bt < 2; bt++) {
                uint32_t addr = bbf + b_k + (uint32_t)(k16 * 16) * 144 + b_c + bt * 32;
                uint32_t r0, r1, r2, r3;
                ldmat_x4_t(r0, r1, r2, r3, addr);
                bf[2 * bt + 0][0] = r0; bf[2 * bt + 0][1] = r1;
                bf[2 * bt + 1][0] = r2; bf[2 * bt + 1][1] = r3;
            }
#pragma unroll
            for (int mt = 0; mt < 2; mt++)
#pragma unroll
                for (int nt = 0; nt < 4; nt++)
                    mma_bf16(acc[mt][nt], af[mt], bf[nt]);
        }
    }
#undef K_ISSUE

    float* outp = kp + (size_t)z * NP * (SA * DKK);
#pragma unroll
    for (int mt = 0; mt < 2; mt++) {
        int row = m0 + warp_m * 32 + mt * 16 + (lane >> 2);
        float* c0 = outp + (size_t)row * 256;
        float* c1 = outp + (size_t)(row + 8) * 256;
#pragma unroll
        for (int nt = 0; nt < 4; nt++) {
            int col = n0 + warp_n * 32 + nt * 8 + (lane & 3) * 2;
            *(float2*)(c0 + col) = make_float2(acc[mt][nt][0], acc[mt][nt][1]);
            *(float2*)(c1 + col) = make_float2(acc[mt][nt][2], acc[mt][nt][3]);
        }
    }
}

// ---------------- reduce partials -> keys output + normalized keys ----------------
__global__ void knorm_kernel(const float* __restrict__ kp, float* __restrict__ keys,
                             float* __restrict__ kn)
{
    int n = blockIdx.x, a = blockIdx.y, tid = threadIdx.x;  // 64 threads
    size_t idx = (size_t)n * (SA * DKK) + a * DKK + tid;
    float v = 0.0f;
#pragma unroll
    for (int ks = 0; ks < KZ; ks++) v += kp[(size_t)ks * NP * (SA * DKK) + idx];
    keys[idx] = v;
    float ss = v * v;
#pragma unroll
    for (int o = 16; o; o >>= 1) ss += __shfl_xor_sync(0xffffffffu, ss, o);
    __shared__ float r2[2];
    if ((tid & 31) == 0) r2[tid >> 5] = ss;
    __syncthreads();
    float nrm = sqrtf(r2[0] + r2[1]);
    kn[idx] = v / (nrm + 1e-8f);
}

// ---------------- queries ----------------
__global__ void q_kernel(const float* __restrict__ hA, const float* __restrict__ WQ,
                         const float* __restrict__ logits, float* __restrict__ qw)
{
    int b = blockIdx.x, a = blockIdx.y, tid = threadIdx.x;  // 64 threads
    __shared__ float hs[DA];
    for (int i = tid; i < DA; i += 64) hs[i] = hA[(size_t)b * DA + i];
    __syncthreads();
    float q = 0.0f;
    const float* w = WQ + (size_t)a * DA * DKK + tid;
#pragma unroll 4
    for (int d = 0; d < DA; d++) q += hs[d] * w[(size_t)d * DKK];
    float ss = q * q;
#pragma unroll
    for (int o = 16; o; o >>= 1) ss += __shfl_xor_sync(0xffffffffu, ss, o);
    __shared__ float r2[2];
    if ((tid & 31) == 0) r2[tid >> 5] = ss;
    __syncthreads();
    float nrm = sqrtf(r2[0] + r2[1]);
    float l0 = logits[0], l1 = logits[1], l2 = logits[2], l3 = logits[3];
    float m = fmaxf(fmaxf(l0, l1), fmaxf(l2, l3));
    float e0 = expf(l0 - m), e1 = expf(l1 - m), e2 = expf(l2 - m), e3 = expf(l3 - m);
    float ea = (a == 0) ? e0 : (a == 1) ? e1 : (a == 2) ? e2 : e3;
    float wa = ea / (e0 + e1 + e2 + e3);
    qw[(size_t)b * (SA * DKK) + a * DKK + tid] = wa * q / (nrm + 1e-8f);
}

// ---------------- scores + gate/exp -> alpha_raw ----------------
__global__ void scores_kernel(const float* __restrict__ QW, const float* __restrict__ KN,
                              const float* __restrict__ tau_p, float* __restrict__ alpha)
{
    int n0 = blockIdx.x * 64, m0 = blockIdx.y * 64;
    __shared__ float As[16][64];
    __shared__ float Bs[16][64];
    int tid = threadIdx.x;
    int am = tid >> 2, ak = (tid & 3) * 4;
    int bn = tid >> 2, bk = (tid & 3) * 4;
    int ty = tid >> 4, tx = tid & 15;
    float acc[4][4] = {};
    for (int k0 = 0; k0 < 256; k0 += 16) {
        float4 av = *(const float4*)(QW + (size_t)(m0 + am) * 256 + k0 + ak);
        As[ak + 0][am] = av.x; As[ak + 1][am] = av.y; As[ak + 2][am] = av.z; As[ak + 3][am] = av.w;
        float4 bv = *(const float4*)(KN + (size_t)(n0 + bn) * 256 + k0 + bk);
        Bs[bk + 0][bn] = bv.x; Bs[bk + 1][bn] = bv.y; Bs[bk + 2][bn] = bv.z; Bs[bk + 3][bn] = bv.w;
        __syncthreads();
#pragma unroll
        for (int kk = 0; kk < 16; kk++) {
            float ar[4], br[4];
            *(float4*)ar = *(const float4*)&As[kk][ty * 4];
            *(float4*)br = *(const float4*)&Bs[kk][tx * 4];
#pragma unroll
            for (int i = 0; i < 4; i++)
#pragma unroll
                for (int j = 0; j < 4; j++) acc[i][j] += ar[i] * br[j];
        }
        __syncthreads();
    }
    float tau = tau_p[0];
#pragma unroll
    for (int i = 0; i < 4; i++)
#pragma unroll
        for (int j = 0; j < 4; j++) {
            float s = acc[i][j];
            float g = 1.0f / (1.0f + expf(-(s - tau)));
            alpha[(size_t)(m0 + ty * 4 + i) * NP + n0 + tx * 4 + j] = g * expf(s);
        }
}

// ---------------- alpha row normalization (+ bf16 copy) ----------------
__global__ void alpha_norm_kernel(float* __restrict__ alpha, __nv_bfloat16* __restrict__ ab)
{
    int b = blockIdx.x, tid = threadIdx.x;  // 256 threads
    float* row = alpha + (size_t)b * NP;
    __nv_bfloat16* rowb = ab + (size_t)b * NP;
    float loc[8]; float s = 0.0f;
#pragma unroll
    for (int i = 0; i < 8; i++) { loc[i] = row[tid + 256 * i]; s += loc[i]; }
#pragma unroll
    for (int o = 16; o; o >>= 1) s += __shfl_xor_sync(0xffffffffu, s, o);
    __shared__ float red[8];
    if ((tid & 31) == 0) red[tid >> 5] = s;
    __syncthreads();
    float tot = 0.0f;
#pragma unroll
    for (int i = 0; i < 8; i++) tot += red[i];
    float inv = 1.0f / (tot + 1e-8f);
#pragma unroll
    for (int i = 0; i < 8; i++) {
        float v = loc[i] * inv;
        row[tid + 256 * i] = v;
        rowb[tid + 256 * i] = __float2bfloat16(v);
    }
}

// ---------------- UV[n] = U_n @ V_n -> bf16, natural [k][de] layout ----------------
__global__ void uv_kernel(const float* __restrict__ pool, __nv_bfloat16* __restrict__ UV)
{
    int n = blockIdx.x, tid = threadIdx.x;  // 256 threads
    __shared__ float Us[DB * RR];
    const float* p = pool + (size_t)n * DP;
    for (int i = tid; i < DB * RR; i += 256) Us[i] = p[i];
    float v[RR];
#pragma unroll
    for (int r = 0; r < RR; r++) v[r] = p[2048 + r * 256 + tid];
    __syncthreads();
    __nv_bfloat16* out = UV + (size_t)n * NDE + tid;
#pragma unroll 2
    for (int d = 0; d < DB; d++) {
        float acc = 0.0f;
#pragma unroll
        for (int r = 0; r < RR; r++) acc += Us[d * RR + r] * v[r];
        out[(size_t)d * 256] = __float2bfloat16(acc);
    }
}

// ---------------- BIG GEMM v5: BM=256 x BN=64, 3-stage ring, 1 barrier/chunk ----------------
#define B4_ABY (256 * 80)   // 20480 B per A stage
#define B4_BBY (32 * 144)   // 4608 B per B stage
#define B4_STG (B4_ABY + B4_BBY)          // 25088 B
#define B4_SMEM (3 * B4_STG)              // 75264 B (dynamic)

__global__ void __launch_bounds__(256, 2) big_mma_kernel(
    const __nv_bfloat16* __restrict__ Ab, const __nv_bfloat16* __restrict__ Bb,
    const float* __restrict__ Wbase, float* __restrict__ C)
{
    extern __shared__ __align__(16) char dsm[];
    int tid = threadIdx.x, lane = tid & 31, wid = tid >> 5;
    int warp_m = wid;                 // 0..7, rows warp_m*32 .. +31
    int n0 = blockIdx.x * 64;

    uint32_t sa = smem_u32(dsm);

    int ar = tid >> 2, aseg = tid & 3;     // A: rows ar+{0,64,128,192}, 4 segs (64B data/row)
    int br = tid >> 3, bseg = tid & 7;     // B: 32 rows x 8 segs of 16B (128B data/row)
    const __nv_bfloat16* Agb = Ab;
    const __nv_bfloat16* Bgb = Bb + n0;

    float acc[2][8][4];
#pragma unroll
    for (int i = 0; i < 2; i++)
#pragma unroll
        for (int j = 0; j < 8; j++)
#pragma unroll
            for (int q = 0; q < 4; q++) acc[i][j][q] = 0.0f;

    const int NC = NP / 32;   // 64
#define B_ISSUE(cc, ss) do { \
    uint32_t ab = sa + (ss) * B4_STG, bbf = ab + B4_ABY; \
    cpa16(ab + (uint32_t)ar * 80 + aseg * 16, Agb + (size_t)ar * NP + (cc) * 32 + aseg * 8); \
    cpa16(ab + (uint32_t)(ar + 64) * 80 + aseg * 16, Agb + (size_t)(ar + 64) * NP + (cc) * 32 + aseg * 8); \
    cpa16(ab + (uint32_t)(ar + 128) * 80 + aseg * 16, Agb + (size_t)(ar + 128) * NP + (cc) * 32 + aseg * 8); \
    cpa16(ab + (uint32_t)(ar + 192) * 80 + aseg * 16, Agb + (size_t)(ar + 192) * NP + (cc) * 32 + aseg * 8); \
    cpa16(bbf + (uint32_t)br * 144 + bseg * 16, Bgb + (size_t)((cc) * 32 + br) * NDE + bseg * 8); \
} while (0)

    B_ISSUE(0, 0); CP_COMMIT();
    B_ISSUE(1, 1); CP_COMMIT();

    uint32_t a_lm = (uint32_t)(warp_m * 32 + (lane & 15)) * 80 + (lane >> 4) * 16;
    uint32_t b_k = (uint32_t)(lane & 15) * 144;
    uint32_t b_c = (uint32_t)(lane >> 4) * 16;

    // stage index of chunk c is c % 3
    int stg = 0;
    for (int c = 0; c < NC; c++) {
        CP_WAIT1();                 // chunk c landed (only c+1 may remain in flight)
        __syncthreads();            // all warps done with compute(c-1); its stage is free
        if (c + 2 < NC) {
            int ns = stg + 2; if (ns >= 3) ns -= 3;
            B_ISSUE(c + 2, ns);
        }
        CP_COMMIT();
        uint32_t ab = sa + stg * B4_STG, bbf = ab + B4_ABY;
#pragma unroll
        for (int k16 = 0; k16 < 2; k16++) {
            uint32_t af[2][4];
            uint32_t bf[8][2];
#pragma unroll
            for (int mt = 0; mt < 2; mt++)
                ldmat_x4(af[mt][0], af[mt][1], af[mt][2], af[mt][3],
                         ab + a_lm + mt * 16 * 80 + k16 * 32);
#pragma unroll
            for (int bt = 0; bt < 4; bt++) {
                uint32_t addr = bbf + b_k + (uint32_t)(k16 * 16) * 144 + b_c + bt * 32;
                uint32_t r0, r1, r2, r3;
                ldmat_x4_t(r0, r1, r2, r3, addr);
                bf[2 * bt + 0][0] = r0; bf[2 * bt + 0][1] = r1;
                bf[2 * bt + 1][0] = r2; bf[2 * bt + 1][1] = r3;
            }
#pragma unroll
            for (int mt = 0; mt < 2; mt++)
#pragma unroll
                for (int nt = 0; nt < 8; nt++)
                    mma_bf16(acc[mt][nt], af[mt], bf[nt]);
        }
        if (++stg == 3) stg = 0;
    }
#undef B_ISSUE

#pragma unroll
    for (int mt = 0; mt < 2; mt++) {
        int row = warp_m * 32 + mt * 16 + (lane >> 2);
        float* c0 = C + (size_t)row * NDE + n0;
        float* c1 = C + (size_t)(row + 8) * NDE + n0;
        const float* wb = Wbase + n0;
#pragma unroll
        for (int nt = 0; nt < 8; nt++) {
            int col = nt * 8 + (lane & 3) * 2;
            float2 w2 = *(const float2*)(wb + col);
            float2 o0, o1;
            o0.x = acc[mt][nt][0] + w2.x; o0.y = acc[mt][nt][1] + w2.y;
            o1.x = acc[mt][nt][2] + w2.x; o1.y = acc[mt][nt][3] + w2.y;
            *(float2*)(c0 + col) = o0;
            *(float2*)(c1 + col) = o1;
        }
    }
}

// ---------------- h_t + residual + LayerNorm (sums b_delta partials) ----------------
__global__ void ht_ln_kernel(const float* __restrict__ Wout, const float* __restrict__ hA,
                             const float* __restrict__ bparts, const float* __restrict__ b_base,
                             const float* __restrict__ gamma_p, const float* __restrict__ ln_s,
                             const float* __restrict__ ln_b, float* __restrict__ hmid)
{
    int b = blockIdx.x, tid = threadIdx.x;     // 256 threads
    int lane = tid & 31, warp = tid >> 5;
    __shared__ float hs[DA];
    __shared__ float ys[DA];
    __shared__ float bsum[DB];
    hs[tid] = hA[(size_t)b * DA + tid];
    {
        float bs = 0.0f;
#pragma unroll
        for (int ks = 0; ks < BDS; ks++)
            bs += bparts[(size_t)ks * BATCH * DB + (size_t)b * DB + tid];
        bsum[tid] = bs;
    }
    __syncthreads();
    float gamma = gamma_p[0];
    const float* Wb = Wout + (size_t)b * NDE;
    for (int c = warp; c < DB; c += 8) {
        const float* row = Wb + (size_t)c * DA;
        float s = 0.0f;
#pragma unroll
        for (int i = 0; i < 8; i++) { int a = lane + 32 * i; s += row[a] * hs[a]; }
#pragma unroll
        for (int o = 16; o; o >>= 1) s += __shfl_xor_sync(0xffffffffu, s, o);
        if (lane == 0) {
            float htv = s + bsum[c] + b_base[c];
            ys[c] = hs[c] + gamma * htv;
        }
    }
    __syncthreads();
    float v = ys[tid];
    float s1 = v, s2 = v * v;
#pragma unroll
    for (int o = 16; o; o >>= 1) {
        s1 += __shfl_xor_sync(0xffffffffu, s1, o);
        s2 += __shfl_xor_sync(0xffffffffu, s2, o);
    }
    __shared__ float red[18];
    if (lane == 0) { red[warp] = s1; red[8 + warp] = s2; }
    __syncthreads();
    if (tid == 0) {
        float a = 0.0f, q = 0.0f;
#pragma unroll
        for (int i = 0; i < 8; i++) { a += red[i]; q += red[8 + i]; }
        red[16] = a / (float)DA;
        red[17] = q / (float)DA;
    }
    __syncthreads();
    float mu = red[16];
    float var = fmaxf(red[17] - mu * mu, 0.0f);
    float r = rsqrtf(var + 1e-6f);
    hmid[(size_t)b * DA + tid] = (v - mu) * r * ln_s[tid] + ln_b[tid];
}

// ---------------- launch ----------------
extern "C" void kernel_launch(void* const* d_in, const int* in_sizes, int n_in,
                              void* d_out, int out_size)
{
    const float* x      = (const float*)d_in[0];
    const float* pool   = (const float*)d_in[1];
    const float* A_w0   = (const float*)d_in[2];
    const float* A_b0   = (const float*)d_in[3];
    const float* A_w1   = (const float*)d_in[4];
    const float* A_b1   = (const float*)d_in[5];
    const float* W_Q    = (const float*)d_in[6];
    const float* W_K    = (const float*)d_in[7];
    const float* logits = (const float*)d_in[8];
    const float* tau    = (const float*)d_in[9];
    const float* W_base = (const float*)d_in[10];
    const float* b_base = (const float*)d_in[11];
    const float* gamma  = (const float*)d_in[12];
    const float* ln_s   = (const float*)d_in[13];
    const float* ln_b   = (const float*)d_in[14];
    const float* B_w0   = (const float*)d_in[15];
    const float* B_b0   = (const float*)d_in[16];
    const float* B_w1   = (const float*)d_in[17];
    const float* B_b1   = (const float*)d_in[18];

    float* out       = (float*)d_out;
    float* out_alpha = out + OUT_ALPHA;
    float* out_W     = out + OUT_W;
    float* out_keys  = out + OUT_KEYS;

    float *p_hid, *p_hA, *p_qw, *p_kn, *p_bt, *p_hmid, *p_hid2, *p_kp;
    __nv_bfloat16 *p_ab, *p_UVb, *p_px, *p_wx;
    cudaGetSymbolAddress((void**)&p_hid,  g_hid);
    cudaGetSymbolAddress((void**)&p_hA,   g_hA);
    cudaGetSymbolAddress((void**)&p_qw,   g_qw);
    cudaGetSymbolAddress((void**)&p_kn,   g_kn);
    cudaGetSymbolAddress((void**)&p_bt,   g_bt);
    cudaGetSymbolAddress((void**)&p_hmid, g_hmid);
    cudaGetSymbolAddress((void**)&p_hid2, g_hid2);
    cudaGetSymbolAddress((void**)&p_kp,   g_kp);
    cudaGetSymbolAddress((void**)&p_ab,   g_alphab);
    cudaGetSymbolAddress((void**)&p_UVb,  g_UVb);
    cudaGetSymbolAddress((void**)&p_px,   g_poolx);
    cudaGetSymbolAddress((void**)&p_wx,   g_wkx);

    cudaFuncSetAttribute(big_mma_kernel, cudaFuncAttributeMaxDynamicSharedMemorySize, B4_SMEM);

    // 1-3) keys prep + UV (keys_mma stays launch #4 -> profiled)
    expand_pool_kernel<<<NP, 256>>>(pool, p_px);
    expand_wk_kernel<<<KEXP, 256>>>(W_K, p_wx);
    uv_kernel<<<NP, 256>>>(pool, p_UVb);
    // 4) keys via split-bf16 tensor-core GEMM  [profiled launch]
    keys_mma_kernel<<<dim3(4, NP / 64, KZ), 128>>>(p_px, p_wx, p_kp);
    // 5) reduce + keys output + k_norm
    knorm_kernel<<<dim3(NP, SA), 64>>>(p_kp, out_keys, p_kn);
    // 6-8) h_A MLP + queries
    gemm64<1><<<dim3(HIDN / 64, BATCH / 64), 256>>>(x, A_w0, A_b0, p_hid, DMODEL, DMODEL, HIDN, HIDN);
    gemm64<0><<<dim3(DA / 64, BATCH / 64), 256>>>(p_hid, A_w1, A_b1, p_hA, HIDN, HIDN, DA, DA);
    q_kernel<<<dim3(BATCH, SA), 64>>>(p_hA, W_Q, logits, p_qw);
    // 9-10) scores -> alpha
    scores_kernel<<<dim3(NP / 64, BATCH / 64), 256>>>(p_qw, p_kn, tau, out_alpha);
    alpha_norm_kernel<<<BATCH, 256>>>(out_alpha, p_ab);
    // 11) W_assembled = W_base + alpha @ UV  (v5: 3-stage ring)
    big_mma_kernel<<<NDE / 64, 256, B4_SMEM>>>(p_ab, p_UVb, W_base, out_W);
    // 12) b_delta split-K=8 partials (128 CTAs)
    bdelta_kernel<<<dim3(DB / 64, BATCH / 64, BDS), 256>>>(out_alpha, pool, p_bt);
    // 13) h_t, residual, layernorm (sums partials)
    ht_ln_kernel<<<BATCH, 256>>>(out_W, p_hA, p_bt, b_base, gamma, ln_s, ln_b, p_hmid);
    // 14-15) output MLP
    gemm64<1><<<dim3(HIDN / 64, BATCH / 64), 256>>>(p_hmid, B_w0, B_b0, p_hid2, DA, DA, HIDN, HIDN);
    gemm64<0><<<dim3(DMODEL / 64, BATCH / 64), 256>>>(p_hid2, B_w1, B_b1, out, HIDN, HIDN, DMODEL, DMODEL);
}

// round 14
// speedup vs baseline: 1.0285x; 1.0285x over previous
#include <cuda_runtime.h>
#include <cuda_bf16.h>
#include <cstdint>
#include <cstddef>

// ---------------- problem constants ----------------
#define BATCH  256
#define DMODEL 512
#define DA     256
#define DB     256
#define RR     8
#define NP     2048
#define DP     4608
#define SA     4
#define DKK    64
#define HIDN   1024
#define NDE    65536           // DB*DA
#define KEXP   13824           // 3*DP (hi | lo | hi)
#define KZ     8               // keys split-K
#define KZLEN  (KEXP / KZ)     // 1728
#define BDS    8               // b_delta split-K
#define BDK    (NP / BDS)      // 256

// output layout (flattened tuple: output, alpha, W_assembled, keys)
#define OUT_ALPHA  (BATCH*DMODEL)
#define OUT_W      (OUT_ALPHA + BATCH*NP)
#define OUT_KEYS   (OUT_W + (size_t)BATCH*DB*DA)

// ---------------- scratch (device globals; no allocation allowed) ----------------
__device__ float g_hid [BATCH*HIDN];
__device__ float g_hA  [BATCH*DA];
__device__ float g_qw  [BATCH*SA*DKK];
__device__ float g_kn  [NP*SA*DKK];
__device__ float g_bt  [BDS*BATCH*DB];                  // b_delta split-K partials (2MB)
__device__ float g_hmid[BATCH*DA];
__device__ float g_hid2[BATCH*HIDN];
__device__ float g_kp  [KZ*NP*SA*DKK];                  // keys split-K partials (16MB)
__device__ __nv_bfloat16 g_alphab[BATCH*NP];            // alpha in bf16
__device__ __nv_bfloat16 g_UVb[(size_t)NP*NDE];         // UV in bf16 (268MB)
__device__ __nv_bfloat16 g_poolx[(size_t)NP*KEXP];      // pool hi/lo expanded (56.6MB)
__device__ __nv_bfloat16 g_wkx[(size_t)KEXP*256];       // W_K hi/lo expanded (7MB)

// ---------------- helpers ----------------
__device__ __forceinline__ float gelu_f(float x) {
    const float c = 0.7978845608028654f;
    return 0.5f * x * (1.0f + tanhf(c * (x + 0.044715f * x * x * x)));
}
__device__ __forceinline__ uint32_t smem_u32(const void* p) {
    uint32_t a;
    asm("{ .reg .u64 t; cvta.to.shared.u64 t, %1; cvt.u32.u64 %0, t; }" : "=r"(a) : "l"(p));
    return a;
}
__device__ __forceinline__ void ldmat_x4(uint32_t& r0, uint32_t& r1, uint32_t& r2, uint32_t& r3,
                                         uint32_t addr) {
    asm volatile("ldmatrix.sync.aligned.m8n8.x4.shared.b16 {%0,%1,%2,%3}, [%4];"
                 : "=r"(r0), "=r"(r1), "=r"(r2), "=r"(r3) : "r"(addr));
}
__device__ __forceinline__ void ldmat_x4_t(uint32_t& r0, uint32_t& r1, uint32_t& r2, uint32_t& r3,
                                           uint32_t addr) {
    asm volatile("ldmatrix.sync.aligned.m8n8.x4.trans.shared.b16 {%0,%1,%2,%3}, [%4];"
                 : "=r"(r0), "=r"(r1), "=r"(r2), "=r"(r3) : "r"(addr));
}
__device__ __forceinline__ void mma_bf16(float* d, const uint32_t* a, const uint32_t* b) {
    asm volatile("mma.sync.aligned.m16n8k16.row.col.f32.bf16.bf16.f32 "
                 "{%0,%1,%2,%3}, {%4,%5,%6,%7}, {%8,%9}, {%0,%1,%2,%3};"
                 : "+f"(d[0]), "+f"(d[1]), "+f"(d[2]), "+f"(d[3])
                 : "r"(a[0]), "r"(a[1]), "r"(a[2]), "r"(a[3]), "r"(b[0]), "r"(b[1]));
}
__device__ __forceinline__ void cpa16(uint32_t dst, const void* src) {
    asm volatile("cp.async.cg.shared.global [%0], [%1], 16;" :: "r"(dst), "l"(src));
}
#define CP_COMMIT() asm volatile("cp.async.commit_group;" ::: "memory")
#define CP_WAIT1()  asm volatile("cp.async.wait_group 1;" ::: "memory")
#define CP_WAIT2()  asm volatile("cp.async.wait_group 2;" ::: "memory")

// ---------------- generic 64x64x16 SGEMM (small MLPs) ----------------
template <int ACT>
__global__ void gemm64(const float* __restrict__ A, const float* __restrict__ B,
                       const float* __restrict__ bias, float* __restrict__ C,
                       int K, int lda, int ldb, int ldc)
{
    __shared__ float As[16][64];
    __shared__ float Bs[16][64];
    int tid = threadIdx.x;
    int m0 = blockIdx.y * 64, n0 = blockIdx.x * 64;
    int am = tid >> 2, ak = (tid & 3) * 4;
    int bk = tid >> 4, bn = (tid & 15) * 4;
    int ty = tid >> 4, tx = tid & 15;
    float acc[4][4] = {};
    const float* Ap = A + (size_t)(m0 + am) * lda + ak;
    const float* Bp = B + (size_t)bk * ldb + n0 + bn;
    float4 av = *(const float4*)Ap;
    float4 bv = *(const float4*)Bp;
    for (int k0 = 0; k0 < K; k0 += 16) {
        As[ak + 0][am] = av.x; As[ak + 1][am] = av.y; As[ak + 2][am] = av.z; As[ak + 3][am] = av.w;
        *(float4*)&Bs[bk][bn] = bv;
        __syncthreads();
        if (k0 + 16 < K) {
            av = *(const float4*)(Ap + (k0 + 16));
            bv = *(const float4*)(Bp + (size_t)(k0 + 16) * ldb);
        }
#pragma unroll
        for (int kk = 0; kk < 16; kk++) {
            float ar[4], br[4];
            *(float4*)ar = *(const float4*)&As[kk][ty * 4];
            *(float4*)br = *(const float4*)&Bs[kk][tx * 4];
#pragma unroll
            for (int i = 0; i < 4; i++)
#pragma unroll
                for (int j = 0; j < 4; j++) acc[i][j] += ar[i] * br[j];
        }
        __syncthreads();
    }
#pragma unroll
    for (int i = 0; i < 4; i++) {
        int m = m0 + ty * 4 + i;
#pragma unroll
        for (int j = 0; j < 4; j++) {
            int n = n0 + tx * 4 + j;
            float c = acc[i][j];
            if (bias) c += bias[n];
            if (ACT == 1) c = gelu_f(c);
            C[(size_t)m * ldc + n] = c;
        }
    }
}

// ---------------- b_delta split-K: partial[z] = alpha[:,kz] @ bias[kz,:] ----------------
__global__ void bdelta_kernel(const float* __restrict__ alpha, const float* __restrict__ pool,
                              float* __restrict__ bt)
{
    __shared__ float As[16][64];
    __shared__ float Bs[16][64];
    int tid = threadIdx.x;
    int m0 = blockIdx.y * 64, n0 = blockIdx.x * 64;
    int z = blockIdx.z;
    int kbeg = z * BDK;
    int am = tid >> 2, ak = (tid & 3) * 4;
    int bk = tid >> 4, bn = (tid & 15) * 4;
    int ty = tid >> 4, tx = tid & 15;
    float acc[4][4] = {};
    const float* Ap = alpha + (size_t)(m0 + am) * NP + kbeg + ak;
    const float* Bp = pool + 4096 + (size_t)(kbeg + bk) * DP + n0 + bn;
    float4 av = *(const float4*)Ap;
    float4 bv = *(const float4*)Bp;
    for (int k0 = 0; k0 < BDK; k0 += 16) {
        As[ak + 0][am] = av.x; As[ak + 1][am] = av.y; As[ak + 2][am] = av.z; As[ak + 3][am] = av.w;
        *(float4*)&Bs[bk][bn] = bv;
        __syncthreads();
        if (k0 + 16 < BDK) {
            av = *(const float4*)(Ap + (k0 + 16));
            bv = *(const float4*)(Bp + (size_t)(k0 + 16) * DP);
        }
#pragma unroll
        for (int kk = 0; kk < 16; kk++) {
            float ar[4], br[4];
            *(float4*)ar = *(const float4*)&As[kk][ty * 4];
            *(float4*)br = *(const float4*)&Bs[kk][tx * 4];
#pragma unroll
            for (int i = 0; i < 4; i++)
#pragma unroll
                for (int j = 0; j < 4; j++) acc[i][j] += ar[i] * br[j];
        }
        __syncthreads();
    }
    float* outp = bt + (size_t)z * BATCH * DB;
#pragma unroll
    for (int i = 0; i < 4; i++)
#pragma unroll
        for (int j = 0; j < 4; j++)
            outp[(size_t)(m0 + ty * 4 + i) * DB + n0 + tx * 4 + j] = acc[i][j];
}

// ---------------- hi/lo expansion: pool -> poolx [n][hi|lo|hi] ----------------
__global__ void expand_pool_kernel(const float* __restrict__ pool, __nv_bfloat16* __restrict__ px)
{
    int n = blockIdx.x, tid = threadIdx.x;
    const float* src = pool + (size_t)n * DP;
    __nv_bfloat16* dst = px + (size_t)n * KEXP;
#pragma unroll 2
    for (int p = tid; p < DP; p += 256) {
        float x = src[p];
        __nv_bfloat16 hi = __float2bfloat16(x);
        __nv_bfloat16 lo = __float2bfloat16(x - __bfloat162float(hi));
        dst[p] = hi;
        dst[DP + p] = lo;
        dst[2 * DP + p] = hi;
    }
}

// ---------------- hi/lo expansion: W_K -> wkx [k][c], c=a*64+q ----------------
__global__ void expand_wk_kernel(const float* __restrict__ WK, __nv_bfloat16* __restrict__ wx)
{
    int k = blockIdx.x, c = threadIdx.x;   // 13824 blocks x 256 threads
    int s = k / DP, p = k % DP;
    int a = c >> 6, q = c & 63;
    float x = WK[(size_t)a * DP * DKK + (size_t)p * DKK + q];
    __nv_bfloat16 hi = __float2bfloat16(x);
    __nv_bfloat16 v;
    if (s < 2) v = hi;
    else v = __float2bfloat16(x - __bfloat162float(hi));
    wx[(size_t)k * 256 + c] = v;
}

// ---------------- keys mma v3: 4-stage cp.async ring, 1 barrier/chunk ----------------
// BM=64, BN=64, BK=32, 128 threads (2m x 2n warps), KZ=8 split-K.
#define K_ABY (64 * 80)     // 5120 B
#define K_BBY (32 * 144)    // 4608 B
#define K_STG (K_ABY + K_BBY)

__global__ void __launch_bounds__(128, 4) keys_mma_kernel(
    const __nv_bfloat16* __restrict__ Ax, const __nv_bfloat16* __restrict__ Bx,
    float* __restrict__ kp)
{
    __shared__ __align__(16) char smem[4 * K_STG];   // 38912 B
    int tid = threadIdx.x, lane = tid & 31, wid = tid >> 5;
    int warp_m = wid & 1, warp_n = wid >> 1;
    int n0 = blockIdx.x * 64;
    int m0 = blockIdx.y * 64;
    int z  = blockIdx.z;
    int kbase = z * KZLEN;

    uint32_t sbase = smem_u32(smem);
    int ar = tid >> 2, aseg = tid & 3;
    int br = tid >> 3, bseg = tid & 7;
    const __nv_bfloat16* Agb = Ax + (size_t)m0 * KEXP + kbase;
    const __nv_bfloat16* Bgb = Bx + (size_t)kbase * 256 + n0;

    float acc[2][4][4];
#pragma unroll
    for (int i = 0; i < 2; i++)
#pragma unroll
        for (int j = 0; j < 4; j++)
#pragma unroll
            for (int q = 0; q < 4; q++) acc[i][j][q] = 0.0f;

    const int NC = KZLEN / 32;   // 54
#define K_ISSUE(cc, ss) do { \
    uint32_t ab = sbase + (ss) * K_STG, bbf = ab + K_ABY; \
    cpa16(ab + (uint32_t)ar * 80 + aseg * 16, Agb + (size_t)ar * KEXP + (cc) * 32 + aseg * 8); \
    cpa16(ab + (uint32_t)(ar + 32) * 80 + aseg * 16, Agb + (size_t)(ar + 32) * KEXP + (cc) * 32 + aseg * 8); \
    cpa16(bbf + (uint32_t)br * 144 + bseg * 16, Bgb + (size_t)((cc) * 32 + br) * 256 + bseg * 8); \
    cpa16(bbf + (uint32_t)(br + 16) * 144 + bseg * 16, Bgb + (size_t)((cc) * 32 + br + 16) * 256 + bseg * 8); \
} while (0)

    K_ISSUE(0, 0); CP_COMMIT();
    K_ISSUE(1, 1); CP_COMMIT();
    K_ISSUE(2, 2); CP_COMMIT();

    uint32_t a_lm = (uint32_t)(warp_m * 32 + (lane & 15)) * 80 + (lane >> 4) * 16;
    uint32_t b_k = (uint32_t)(lane & 15) * 144;
    uint32_t b_c = (uint32_t)(warp_n * 32 + (lane >> 4) * 8) * 2;

    for (int c = 0; c < NC; c++) {
        CP_WAIT2();
        __syncthreads();
        if (c + 3 < NC) K_ISSUE(c + 3, (c + 3) & 3);
        CP_COMMIT();
        uint32_t ab = sbase + (c & 3) * K_STG, bbf = ab + K_ABY;
#pragma unroll
        for (int k16 = 0; k16 < 2; k16++) {
            uint32_t af[2][4];
            uint32_t bf[4][2];
#pragma unroll
            for (int mt = 0; mt < 2; mt++)
                ldmat_x4(af[mt][0], af[mt][1], af[mt][2], af[mt][3],
                         ab + a_lm + mt * 16 * 80 + k16 * 32);
#pragma unroll
            for (int bt = 0; bt < 2; bt++) {
                uint32_t addr = bbf + b_k + (uint32_t)(k16 * 16) * 144 + b_c + bt * 32;
                uint32_t r0, r1, r2, r3;
                ldmat_x4_t(r0, r1, r2, r3, addr);
                bf[2 * bt + 0][0] = r0; bf[2 * bt + 0][1] = r1;
                bf[2 * bt + 1][0] = r2; bf[2 * bt + 1][1] = r3;
            }
#pragma unroll
            for (int mt = 0; mt < 2; mt++)
#pragma unroll
                for (int nt = 0; nt < 4; nt++)
                    mma_bf16(acc[mt][nt], af[mt], bf[nt]);
        }
    }
#undef K_ISSUE

    float* outp = kp + (size_t)z * NP * (SA * DKK);
#pragma unroll
    for (int mt = 0; mt < 2; mt++) {
        int row = m0 + warp_m * 32 + mt * 16 + (lane >> 2);
        float* c0 = outp + (size_t)row * 256;
        float* c1 = outp + (size_t)(row + 8) * 256;
#pragma unroll
        for (int nt = 0; nt < 4; nt++) {
            int col = n0 + warp_n * 32 + nt * 8 + (lane & 3) * 2;
            *(float2*)(c0 + col) = make_float2(acc[mt][nt][0], acc[mt][nt][1]);
            *(float2*)(c1 + col) = make_float2(acc[mt][nt][2], acc[mt][nt][3]);
        }
    }
}

// ---------------- reduce partials -> keys output + normalized keys ----------------
__global__ void knorm_kernel(const float* __restrict__ kp, float* __restrict__ keys,
                             float* __restrict__ kn)
{
    int n = blockIdx.x, a = blockIdx.y, tid = threadIdx.x;  // 64 threads
    size_t idx = (size_t)n * (SA * DKK) + a * DKK + tid;
    float v = 0.0f;
#pragma unroll
    for (int ks = 0; ks < KZ; ks++) v += kp[(size_t)ks * NP * (SA * DKK) + idx];
    keys[idx] = v;
    float ss = v * v;
#pragma unroll
    for (int o = 16; o; o >>= 1) ss += __shfl_xor_sync(0xffffffffu, ss, o);
    __shared__ float r2[2];
    if ((tid & 31) == 0) r2[tid >> 5] = ss;
    __syncthreads();
    float nrm = sqrtf(r2[0] + r2[1]);
    kn[idx] = v / (nrm + 1e-8f);
}

// ---------------- queries ----------------
__global__ void q_kernel(const float* __restrict__ hA, const float* __restrict__ WQ,
                         const float* __restrict__ logits, float* __restrict__ qw)
{
    int b = blockIdx.x, a = blockIdx.y, tid = threadIdx.x;  // 64 threads
    __shared__ float hs[DA];
    for (int i = tid; i < DA; i += 64) hs[i] = hA[(size_t)b * DA + i];
    __syncthreads();
    float q = 0.0f;
    const float* w = WQ + (size_t)a * DA * DKK + tid;
#pragma unroll 4
    for (int d = 0; d < DA; d++) q += hs[d] * w[(size_t)d * DKK];
    float ss = q * q;
#pragma unroll
    for (int o = 16; o; o >>= 1) ss += __shfl_xor_sync(0xffffffffu, ss, o);
    __shared__ float r2[2];
    if ((tid & 31) == 0) r2[tid >> 5] = ss;
    __syncthreads();
    float nrm = sqrtf(r2[0] + r2[1]);
    float l0 = logits[0], l1 = logits[1], l2 = logits[2], l3 = logits[3];
    float m = fmaxf(fmaxf(l0, l1), fmaxf(l2, l3));
    float e0 = expf(l0 - m), e1 = expf(l1 - m), e2 = expf(l2 - m), e3 = expf(l3 - m);
    float ea = (a == 0) ? e0 : (a == 1) ? e1 : (a == 2) ? e2 : e3;
    float wa = ea / (e0 + e1 + e2 + e3);
    qw[(size_t)b * (SA * DKK) + a * DKK + tid] = wa * q / (nrm + 1e-8f);
}

// ---------------- scores + gate/exp -> alpha_raw ----------------
__global__ void scores_kernel(const float* __restrict__ QW, const float* __restrict__ KN,
                              const float* __restrict__ tau_p, float* __restrict__ alpha)
{
    int n0 = blockIdx.x * 64, m0 = blockIdx.y * 64;
    __shared__ float As[16][64];
    __shared__ float Bs[16][64];
    int tid = threadIdx.x;
    int am = tid >> 2, ak = (tid & 3) * 4;
    int bn = tid >> 2, bk = (tid & 3) * 4;
    int ty = tid >> 4, tx = tid & 15;
    float acc[4][4] = {};
    for (int k0 = 0; k0 < 256; k0 += 16) {
        float4 av = *(const float4*)(QW + (size_t)(m0 + am) * 256 + k0 + ak);
        As[ak + 0][am] = av.x; As[ak + 1][am] = av.y; As[ak + 2][am] = av.z; As[ak + 3][am] = av.w;
        float4 bv = *(const float4*)(KN + (size_t)(n0 + bn) * 256 + k0 + bk);
        Bs[bk + 0][bn] = bv.x; Bs[bk + 1][bn] = bv.y; Bs[bk + 2][bn] = bv.z; Bs[bk + 3][bn] = bv.w;
        __syncthreads();
#pragma unroll
        for (int kk = 0; kk < 16; kk++) {
            float ar[4], br[4];
            *(float4*)ar = *(const float4*)&As[kk][ty * 4];
            *(float4*)br = *(const float4*)&Bs[kk][tx * 4];
#pragma unroll
            for (int i = 0; i < 4; i++)
#pragma unroll
                for (int j = 0; j < 4; j++) acc[i][j] += ar[i] * br[j];
        }
        __syncthreads();
    }
    float tau = tau_p[0];
#pragma unroll
    for (int i = 0; i < 4; i++)
#pragma unroll
        for (int j = 0; j < 4; j++) {
            float s = acc[i][j];
            float g = 1.0f / (1.0f + expf(-(s - tau)));
            alpha[(size_t)(m0 + ty * 4 + i) * NP + n0 + tx * 4 + j] = g * expf(s);
        }
}

// ---------------- alpha row normalization (+ bf16 copy) ----------------
__global__ void alpha_norm_kernel(float* __restrict__ alpha, __nv_bfloat16* __restrict__ ab)
{
    int b = blockIdx.x, tid = threadIdx.x;  // 256 threads
    float* row = alpha + (size_t)b * NP;
    __nv_bfloat16* rowb = ab + (size_t)b * NP;
    float loc[8]; float s = 0.0f;
#pragma unroll
    for (int i = 0; i < 8; i++) { loc[i] = row[tid + 256 * i]; s += loc[i]; }
#pragma unroll
    for (int o = 16; o; o >>= 1) s += __shfl_xor_sync(0xffffffffu, s, o);
    __shared__ float red[8];
    if ((tid & 31) == 0) red[tid >> 5] = s;
    __syncthreads();
    float tot = 0.0f;
#pragma unroll
    for (int i = 0; i < 8; i++) tot += red[i];
    float inv = 1.0f / (tot + 1e-8f);
#pragma unroll
    for (int i = 0; i < 8; i++) {
        float v = loc[i] * inv;
        row[tid + 256 * i] = v;
        rowb[tid + 256 * i] = __float2bfloat16(v);
    }
}

// ---------------- UV[n] = U_n @ V_n -> bf16, natural [k][de] layout ----------------
__global__ void uv_kernel(const float* __restrict__ pool, __nv_bfloat16* __restrict__ UV)
{
    int n = blockIdx.x, tid = threadIdx.x;  // 256 threads
    __shared__ float Us[DB * RR];
    const float* p = pool + (size_t)n * DP;
    for (int i = tid; i < DB * RR; i += 256) Us[i] = p[i];
    float v[RR];
#pragma unroll
    for (int r = 0; r < RR; r++) v[r] = p[2048 + r * 256 + tid];
    __syncthreads();
    __nv_bfloat16* out = UV + (size_t)n * NDE + tid;
#pragma unroll 2
    for (int d = 0; d < DB; d++) {
        float acc = 0.0f;
#pragma unroll
        for (int r = 0; r < RR; r++) acc += Us[d * RR + r] * v[r];
        out[(size_t)d * 256] = __float2bfloat16(acc);
    }
}

// ---------------- BIG GEMM v4 (R12-proven): BM=256 x BN=64, 2-stage ----------------
#define B4_ABY (256 * 80)   // 20480 B per A stage
#define B4_BBY (32 * 144)   // 4608 B per B stage
#define B4_STG (B4_ABY + B4_BBY)
#define B4_SMEM (2 * B4_STG)   // 50176 B (dynamic)

__global__ void __launch_bounds__(256, 2) big_mma_kernel(
    const __nv_bfloat16* __restrict__ Ab, const __nv_bfloat16* __restrict__ Bb,
    const float* __restrict__ Wbase, float* __restrict__ C)
{
    extern __shared__ __align__(16) char dsm[];
    int tid = threadIdx.x, lane = tid & 31, wid = tid >> 5;
    int warp_m = wid;                 // 0..7, rows warp_m*32 .. +31
    int n0 = blockIdx.x * 64;

    uint32_t sa = smem_u32(dsm);

    int ar = tid >> 2, aseg = tid & 3;     // A: rows ar+{0,64,128,192}, 4 segs (64B data/row)
    int br = tid >> 3, bseg = tid & 7;     // B: 32 rows x 8 segs of 16B (128B data/row)
    const __nv_bfloat16* Agb = Ab;
    const __nv_bfloat16* Bgb = Bb + n0;

    float acc[2][8][4];
#pragma unroll
    for (int i = 0; i < 2; i++)
#pragma unroll
        for (int j = 0; j < 8; j++)
#pragma unroll
            for (int q = 0; q < 4; q++) acc[i][j][q] = 0.0f;

    const int NC = NP / 32;   // 64
#define B_ISSUE(cc, ss) do { \
    uint32_t ab = sa + (ss) * B4_STG, bbf = ab + B4_ABY; \
    cpa16(ab + (uint32_t)ar * 80 + aseg * 16, Agb + (size_t)ar * NP + (cc) * 32 + aseg * 8); \
    cpa16(ab + (uint32_t)(ar + 64) * 80 + aseg * 16, Agb + (size_t)(ar + 64) * NP + (cc) * 32 + aseg * 8); \
    cpa16(ab + (uint32_t)(ar + 128) * 80 + aseg * 16, Agb + (size_t)(ar + 128) * NP + (cc) * 32 + aseg * 8); \
    cpa16(ab + (uint32_t)(ar + 192) * 80 + aseg * 16, Agb + (size_t)(ar + 192) * NP + (cc) * 32 + aseg * 8); \
    cpa16(bbf + (uint32_t)br * 144 + bseg * 16, Bgb + (size_t)((cc) * 32 + br) * NDE + bseg * 8); \
} while (0)

    B_ISSUE(0, 0); CP_COMMIT();
    B_ISSUE(1, 1); CP_COMMIT();
    CP_WAIT1(); __syncthreads();

    uint32_t a_lm = (uint32_t)(warp_m * 32 + (lane & 15)) * 80 + (lane >> 4) * 16;
    uint32_t b_k = (uint32_t)(lane & 15) * 144;
    uint32_t b_c = (uint32_t)(lane >> 4) * 16;

    for (int c = 0; c < NC; c++) {
        int buf = c & 1;
        uint32_t ab = sa + buf * B4_STG, bbf = ab + B4_ABY;
#pragma unroll
        for (int k16 = 0; k16 < 2; k16++) {
            uint32_t af[2][4];
            uint32_t bf[8][2];
#pragma unroll
            for (int mt = 0; mt < 2; mt++)
                ldmat_x4(af[mt][0], af[mt][1], af[mt][2], af[mt][3],
                         ab + a_lm + mt * 16 * 80 + k16 * 32);
#pragma unroll
            for (int bt = 0; bt < 4; bt++) {
                uint32_t addr = bbf + b_k + (uint32_t)(k16 * 16) * 144 + b_c + bt * 32;
                uint32_t r0, r1, r2, r3;
                ldmat_x4_t(r0, r1, r2, r3, addr);
                bf[2 * bt + 0][0] = r0; bf[2 * bt + 0][1] = r1;
                bf[2 * bt + 1][0] = r2; bf[2 * bt + 1][1] = r3;
            }
#pragma unroll
            for (int mt = 0; mt < 2; mt++)
#pragma unroll
                for (int nt = 0; nt < 8; nt++)
                    mma_bf16(acc[mt][nt], af[mt], bf[nt]);
        }
        __syncthreads();
        if (c + 2 < NC) B_ISSUE(c + 2, buf);
        CP_COMMIT();
        CP_WAIT1();
        __syncthreads();
    }
#undef B_ISSUE

#pragma unroll
    for (int mt = 0; mt < 2; mt++) {
        int row = warp_m * 32 + mt * 16 + (lane >> 2);
        float* c0 = C + (size_t)row * NDE + n0;
        float* c1 = C + (size_t)(row + 8) * NDE + n0;
        const float* wb = Wbase + n0;
#pragma unroll
        for (int nt = 0; nt < 8; nt++) {
            int col = nt * 8 + (lane & 3) * 2;
            float2 w2 = *(const float2*)(wb + col);
            float2 o0, o1;
            o0.x = acc[mt][nt][0] + w2.x; o0.y = acc[mt][nt][1] + w2.y;
            o1.x = acc[mt][nt][2] + w2.x; o1.y = acc[mt][nt][3] + w2.y;
            *(float2*)(c0 + col) = o0;
            *(float2*)(c1 + col) = o1;
        }
    }
}

// ---------------- h_t + residual + LayerNorm (sums b_delta partials) ----------------
__global__ void ht_ln_kernel(const float* __restrict__ Wout, const float* __restrict__ hA,
                             const float* __restrict__ bparts, const float* __restrict__ b_base,
                             const float* __restrict__ gamma_p, const float* __restrict__ ln_s,
                             const float* __restrict__ ln_b, float* __restrict__ hmid)
{
    int b = blockIdx.x, tid = threadIdx.x;     // 256 threads
    int lane = tid & 31, warp = tid >> 5;
    __shared__ float hs[DA];
    __shared__ float ys[DA];
    __shared__ float bsum[DB];
    hs[tid] = hA[(size_t)b * DA + tid];
    {
        float bs = 0.0f;
#pragma unroll
        for (int ks = 0; ks < BDS; ks++)
            bs += bparts[(size_t)ks * BATCH * DB + (size_t)b * DB + tid];
        bsum[tid] = bs;
    }
    __syncthreads();
    float gamma = gamma_p[0];
    const float* Wb = Wout + (size_t)b * NDE;
    for (int c = warp; c < DB; c += 8) {
        const float* row = Wb + (size_t)c * DA;
        float s = 0.0f;
#pragma unroll
        for (int i = 0; i < 8; i++) { int a = lane + 32 * i; s += row[a] * hs[a]; }
#pragma unroll
        for (int o = 16; o; o >>= 1) s += __shfl_xor_sync(0xffffffffu, s, o);
        if (lane == 0) {
            float htv = s + bsum[c] + b_base[c];
            ys[c] = hs[c] + gamma * htv;
        }
    }
    __syncthreads();
    float v = ys[tid];
    float s1 = v, s2 = v * v;
#pragma unroll
    for (int o = 16; o; o >>= 1) {
        s1 += __shfl_xor_sync(0xffffffffu, s1, o);
        s2 += __shfl_xor_sync(0xffffffffu, s2, o);
    }
    __shared__ float red[18];
    if (lane == 0) { red[warp] = s1; red[8 + warp] = s2; }
    __syncthreads();
    if (tid == 0) {
        float a = 0.0f, q = 0.0f;
#pragma unroll
        for (int i = 0; i < 8; i++) { a += red[i]; q += red[8 + i]; }
        red[16] = a / (float)DA;
        red[17] = q / (float)DA;
    }
    __syncthreads();
    float mu = red[16];
    float var = fmaxf(red[17] - mu * mu, 0.0f);
    float r = rsqrtf(var + 1e-6f);
    hmid[(size_t)b * DA + tid] = (v - mu) * r * ln_s[tid] + ln_b[tid];
}

// ---------------- launch ----------------
extern "C" void kernel_launch(void* const* d_in, const int* in_sizes, int n_in,
                              void* d_out, int out_size)
{
    const float* x      = (const float*)d_in[0];
    const float* pool   = (const float*)d_in[1];
    const float* A_w0   = (const float*)d_in[2];
    const float* A_b0   = (const float*)d_in[3];
    const float* A_w1   = (const float*)d_in[4];
    const float* A_b1   = (const float*)d_in[5];
    const float* W_Q    = (const float*)d_in[6];
    const float* W_K    = (const float*)d_in[7];
    const float* logits = (const float*)d_in[8];
    const float* tau    = (const float*)d_in[9];
    const float* W_base = (const float*)d_in[10];
    const float* b_base = (const float*)d_in[11];
    const float* gamma  = (const float*)d_in[12];
    const float* ln_s   = (const float*)d_in[13];
    const float* ln_b   = (const float*)d_in[14];
    const float* B_w0   = (const float*)d_in[15];
    const float* B_b0   = (const float*)d_in[16];
    const float* B_w1   = (const float*)d_in[17];
    const float* B_b1   = (const float*)d_in[18];

    float* out       = (float*)d_out;
    float* out_alpha = out + OUT_ALPHA;
    float* out_W     = out + OUT_W;
    float* out_keys  = out + OUT_KEYS;

    float *p_hid, *p_hA, *p_qw, *p_kn, *p_bt, *p_hmid, *p_hid2, *p_kp;
    __nv_bfloat16 *p_ab, *p_UVb, *p_px, *p_wx;
    cudaGetSymbolAddress((void**)&p_hid,  g_hid);
    cudaGetSymbolAddress((void**)&p_hA,   g_hA);
    cudaGetSymbolAddress((void**)&p_qw,   g_qw);
    cudaGetSymbolAddress((void**)&p_kn,   g_kn);
    cudaGetSymbolAddress((void**)&p_bt,   g_bt);
    cudaGetSymbolAddress((void**)&p_hmid, g_hmid);
    cudaGetSymbolAddress((void**)&p_hid2, g_hid2);
    cudaGetSymbolAddress((void**)&p_kp,   g_kp);
    cudaGetSymbolAddress((void**)&p_ab,   g_alphab);
    cudaGetSymbolAddress((void**)&p_UVb,  g_UVb);
    cudaGetSymbolAddress((void**)&p_px,   g_poolx);
    cudaGetSymbolAddress((void**)&p_wx,   g_wkx);

    cudaFuncSetAttribute(big_mma_kernel, cudaFuncAttributeMaxDynamicSharedMemorySize, B4_SMEM);

    // 1-3) keys prep + UV (keys_mma stays launch #4 -> profiled)
    expand_pool_kernel<<<NP, 256>>>(pool, p_px);
    expand_wk_kernel<<<KEXP, 256>>>(W_K, p_wx);
    uv_kernel<<<NP, 256>>>(pool, p_UVb);
    // 4) keys via split-bf16 tensor-core GEMM, KZ=8  [profiled launch]
    keys_mma_kernel<<<dim3(4, NP / 64, KZ), 128>>>(p_px, p_wx, p_kp);
    // 5) reduce + keys output + k_norm
    knorm_kernel<<<dim3(NP, SA), 64>>>(p_kp, out_keys, p_kn);
    // 6-8) h_A MLP + queries
    gemm64<1><<<dim3(HIDN / 64, BATCH / 64), 256>>>(x, A_w0, A_b0, p_hid, DMODEL, DMODEL, HIDN, HIDN);
    gemm64<0><<<dim3(DA / 64, BATCH / 64), 256>>>(p_hid, A_w1, A_b1, p_hA, HIDN, HIDN, DA, DA);
    q_kernel<<<dim3(BATCH, SA), 64>>>(p_hA, W_Q, logits, p_qw);
    // 9-10) scores -> alpha
    scores_kernel<<<dim3(NP / 64, BATCH / 64), 256>>>(p_qw, p_kn, tau, out_alpha);
    alpha_norm_kernel<<<BATCH, 256>>>(out_alpha, p_ab);
    // 11) W_assembled = W_base + alpha @ UV  (v4 2-stage, R12-proven)
    big_mma_kernel<<<NDE / 64, 256, B4_SMEM>>>(p_ab, p_UVb, W_base, out_W);
    // 12) b_delta split-K=8 partials (128 CTAs)
    bdelta_kernel<<<dim3(DB / 64, BATCH / 64, BDS), 256>>>(out_alpha, pool, p_bt);
    // 13) h_t, residual, layernorm (sums partials)
    ht_ln_kernel<<<BATCH, 256>>>(out_W, p_hA, p_bt, b_base, gamma, ln_s, ln_b, p_hmid);
    // 14-15) output MLP
    gemm64<1><<<dim3(HIDN / 64, BATCH / 64), 256>>>(p_hmid, B_w0, B_b0, p_hid2, DA, DA, HIDN, HIDN);
    gemm64<0><<<dim3(DMODEL / 64, BATCH / 64), 256>>>(p_hid2, B_w1, B_b1, out, HIDN, HIDN, DMODEL, DMODEL);
}

// round 15
// speedup vs baseline: 1.0373x; 1.0086x over previous
#include <cuda_runtime.h>
#include <cuda_bf16.h>
#include <cstdint>
#include <cstddef>

// ---------------- problem constants ----------------
#define BATCH  256
#define DMODEL 512
#define DA     256
#define DB     256
#define RR     8
#define NP     2048
#define DP     4608
#define SA     4
#define DKK    64
#define HIDN   1024
#define NDE    65536           // DB*DA
#define KEXP   13824           // 3*DP (hi | lo | hi)
#define KZ     8               // keys split-K
#define KZLEN  (KEXP / KZ)     // 1728
#define BDS    8               // b_delta split-K
#define BDK    (NP / BDS)      // 256

// output layout (flattened tuple: output, alpha, W_assembled, keys)
#define OUT_ALPHA  (BATCH*DMODEL)
#define OUT_W      (OUT_ALPHA + BATCH*NP)
#define OUT_KEYS   (OUT_W + (size_t)BATCH*DB*DA)

// ---------------- scratch (device globals; no allocation allowed) ----------------
__device__ float g_hid [BATCH*HIDN];
__device__ float g_hA  [BATCH*DA];
__device__ float g_qw  [BATCH*SA*DKK];
__device__ float g_kn  [NP*SA*DKK];
__device__ float g_bt  [BDS*BATCH*DB];                  // b_delta split-K partials (2MB)
__device__ float g_hmid[BATCH*DA];
__device__ float g_hid2[BATCH*HIDN];
__device__ float g_kp  [KZ*NP*SA*DKK];                  // keys split-K partials (16MB)
__device__ __nv_bfloat16 g_alphab[BATCH*NP];            // alpha in bf16
__device__ __nv_bfloat16 g_UVb[(size_t)NP*NDE];         // UV in bf16 (268MB)
__device__ __nv_bfloat16 g_poolx[(size_t)NP*KEXP];      // pool hi/lo expanded (56.6MB)
__device__ __nv_bfloat16 g_wkx[(size_t)KEXP*256];       // W_K hi/lo expanded (7MB)

// ---------------- helpers ----------------
__device__ __forceinline__ float gelu_f(float x) {
    const float c = 0.7978845608028654f;
    return 0.5f * x * (1.0f + tanhf(c * (x + 0.044715f * x * x * x)));
}
__device__ __forceinline__ uint32_t smem_u32(const void* p) {
    uint32_t a;
    asm("{ .reg .u64 t; cvta.to.shared.u64 t, %1; cvt.u32.u64 %0, t; }" : "=r"(a) : "l"(p));
    return a;
}
__device__ __forceinline__ void ldmat_x4(uint32_t& r0, uint32_t& r1, uint32_t& r2, uint32_t& r3,
                                         uint32_t addr) {
    asm volatile("ldmatrix.sync.aligned.m8n8.x4.shared.b16 {%0,%1,%2,%3}, [%4];"
                 : "=r"(r0), "=r"(r1), "=r"(r2), "=r"(r3) : "r"(addr));
}
__device__ __forceinline__ void ldmat_x4_t(uint32_t& r0, uint32_t& r1, uint32_t& r2, uint32_t& r3,
                                           uint32_t addr) {
    asm volatile("ldmatrix.sync.aligned.m8n8.x4.trans.shared.b16 {%0,%1,%2,%3}, [%4];"
                 : "=r"(r0), "=r"(r1), "=r"(r2), "=r"(r3) : "r"(addr));
}
__device__ __forceinline__ void mma_bf16(float* d, const uint32_t* a, const uint32_t* b) {
    asm volatile("mma.sync.aligned.m16n8k16.row.col.f32.bf16.bf16.f32 "
                 "{%0,%1,%2,%3}, {%4,%5,%6,%7}, {%8,%9}, {%0,%1,%2,%3};"
                 : "+f"(d[0]), "+f"(d[1]), "+f"(d[2]), "+f"(d[3])
                 : "r"(a[0]), "r"(a[1]), "r"(a[2]), "r"(a[3]), "r"(b[0]), "r"(b[1]));
}
__device__ __forceinline__ void cpa16(uint32_t dst, const void* src) {
    asm volatile("cp.async.cg.shared.global [%0], [%1], 16;" :: "r"(dst), "l"(src));
}
#define CP_COMMIT() asm volatile("cp.async.commit_group;" ::: "memory")
#define CP_WAIT1()  asm volatile("cp.async.wait_group 1;" ::: "memory")
#define CP_WAIT2()  asm volatile("cp.async.wait_group 2;" ::: "memory")

// ---------------- generic 64x64x16 SGEMM (small MLPs) ----------------
template <int ACT>
__global__ void gemm64(const float* __restrict__ A, const float* __restrict__ B,
                       const float* __restrict__ bias, float* __restrict__ C,
                       int K, int lda, int ldb, int ldc)
{
    __shared__ float As[16][64];
    __shared__ float Bs[16][64];
    int tid = threadIdx.x;
    int m0 = blockIdx.y * 64, n0 = blockIdx.x * 64;
    int am = tid >> 2, ak = (tid & 3) * 4;
    int bk = tid >> 4, bn = (tid & 15) * 4;
    int ty = tid >> 4, tx = tid & 15;
    float acc[4][4] = {};
    const float* Ap = A + (size_t)(m0 + am) * lda + ak;
    const float* Bp = B + (size_t)bk * ldb + n0 + bn;
    float4 av = *(const float4*)Ap;
    float4 bv = *(const float4*)Bp;
    for (int k0 = 0; k0 < K; k0 += 16) {
        As[ak + 0][am] = av.x; As[ak + 1][am] = av.y; As[ak + 2][am] = av.z; As[ak + 3][am] = av.w;
        *(float4*)&Bs[bk][bn] = bv;
        __syncthreads();
        if (k0 + 16 < K) {
            av = *(const float4*)(Ap + (k0 + 16));
            bv = *(const float4*)(Bp + (size_t)(k0 + 16) * ldb);
        }
#pragma unroll
        for (int kk = 0; kk < 16; kk++) {
            float ar[4], br[4];
            *(float4*)ar = *(const float4*)&As[kk][ty * 4];
            *(float4*)br = *(const float4*)&Bs[kk][tx * 4];
#pragma unroll
            for (int i = 0; i < 4; i++)
#pragma unroll
                for (int j = 0; j < 4; j++) acc[i][j] += ar[i] * br[j];
        }
        __syncthreads();
    }
#pragma unroll
    for (int i = 0; i < 4; i++) {
        int m = m0 + ty * 4 + i;
#pragma unroll
        for (int j = 0; j < 4; j++) {
            int n = n0 + tx * 4 + j;
            float c = acc[i][j];
            if (bias) c += bias[n];
            if (ACT == 1) c = gelu_f(c);
            C[(size_t)m * ldc + n] = c;
        }
    }
}

// ---------------- hi/lo expansion: pool -> poolx [n][hi|lo|hi] ----------------
__global__ void expand_pool_kernel(const float* __restrict__ pool, __nv_bfloat16* __restrict__ px)
{
    int n = blockIdx.x, tid = threadIdx.x;
    const float* src = pool + (size_t)n * DP;
    __nv_bfloat16* dst = px + (size_t)n * KEXP;
#pragma unroll 2
    for (int p = tid; p < DP; p += 256) {
        float x = src[p];
        __nv_bfloat16 hi = __float2bfloat16(x);
        __nv_bfloat16 lo = __float2bfloat16(x - __bfloat162float(hi));
        dst[p] = hi;
        dst[DP + p] = lo;
        dst[2 * DP + p] = hi;
    }
}

// ---------------- hi/lo expansion: W_K -> wkx [k][c], c=a*64+q ----------------
__global__ void expand_wk_kernel(const float* __restrict__ WK, __nv_bfloat16* __restrict__ wx)
{
    int k = blockIdx.x, c = threadIdx.x;   // 13824 blocks x 256 threads
    int s = k / DP, p = k % DP;
    int a = c >> 6, q = c & 63;
    float x = WK[(size_t)a * DP * DKK + (size_t)p * DKK + q];
    __nv_bfloat16 hi = __float2bfloat16(x);
    __nv_bfloat16 v;
    if (s < 2) v = hi;
    else v = __float2bfloat16(x - __bfloat162float(hi));
    wx[(size_t)k * 256 + c] = v;
}

// ---------------- FUSED: keys mma (blocks 0..1023) + UV build (blocks 1024..3071) ----------------
// keys: BM=64, BN=64, BK=32, 128 threads (2m x 2n warps), KZ=8 split-K, 4-stage ring.
// uv:   n = bid-1024; 128 threads, 2 columns per thread; identical math to old uv_kernel.
#define K_ABY (64 * 80)     // 5120 B
#define K_BBY (32 * 144)    // 4608 B
#define K_STG (K_ABY + K_BBY)

__global__ void __launch_bounds__(128, 4) keys_uv_kernel(
    const __nv_bfloat16* __restrict__ Ax, const __nv_bfloat16* __restrict__ Bx,
    float* __restrict__ kp, const float* __restrict__ pool, __nv_bfloat16* __restrict__ UV)
{
    __shared__ __align__(16) char smem[4 * K_STG];   // 38912 B (uv uses first 8KB as float)
    int tid = threadIdx.x;
    int bid = blockIdx.x;

    if (bid >= 1024) {
        // ---------------- UV branch ----------------
        int n = bid - 1024;
        float* Us = (float*)smem;                     // 2048 floats
        const float* p = pool + (size_t)n * DP;
        for (int i = tid; i < DB * RR; i += 128) Us[i] = p[i];
        float v0[RR], v1[RR];
#pragma unroll
        for (int r = 0; r < RR; r++) {
            v0[r] = p[2048 + r * 256 + tid];
            v1[r] = p[2048 + r * 256 + tid + 128];
        }
        __syncthreads();
        __nv_bfloat16* out = UV + (size_t)n * NDE;
#pragma unroll 2
        for (int d = 0; d < DB; d++) {
            float a0 = 0.0f, a1 = 0.0f;
#pragma unroll
            for (int r = 0; r < RR; r++) {
                a0 += Us[d * RR + r] * v0[r];
                a1 += Us[d * RR + r] * v1[r];
            }
            out[(size_t)d * 256 + tid] = __float2bfloat16(a0);
            out[(size_t)d * 256 + tid + 128] = __float2bfloat16(a1);
        }
        return;
    }

    // ---------------- keys branch ----------------
    int lane = tid & 31, wid = tid >> 5;
    int warp_m = wid & 1, warp_n = wid >> 1;
    int bx = bid & 3, by = (bid >> 2) & 31, z = bid >> 7;
    int n0 = bx * 64;
    int m0 = by * 64;
    int kbase = z * KZLEN;

    uint32_t sbase = smem_u32(smem);
    int ar = tid >> 2, aseg = tid & 3;
    int br = tid >> 3, bseg = tid & 7;
    const __nv_bfloat16* Agb = Ax + (size_t)m0 * KEXP + kbase;
    const __nv_bfloat16* Bgb = Bx + (size_t)kbase * 256 + n0;

    float acc[2][4][4];
#pragma unroll
    for (int i = 0; i < 2; i++)
#pragma unroll
        for (int j = 0; j < 4; j++)
#pragma unroll
            for (int q = 0; q < 4; q++) acc[i][j][q] = 0.0f;

    const int NC = KZLEN / 32;   // 54
#define K_ISSUE(cc, ss) do { \
    uint32_t ab = sbase + (ss) * K_STG, bbf = ab + K_ABY; \
    cpa16(ab + (uint32_t)ar * 80 + aseg * 16, Agb + (size_t)ar * KEXP + (cc) * 32 + aseg * 8); \
    cpa16(ab + (uint32_t)(ar + 32) * 80 + aseg * 16, Agb + (size_t)(ar + 32) * KEXP + (cc) * 32 + aseg * 8); \
    cpa16(bbf + (uint32_t)br * 144 + bseg * 16, Bgb + (size_t)((cc) * 32 + br) * 256 + bseg * 8); \
    cpa16(bbf + (uint32_t)(br + 16) * 144 + bseg * 16, Bgb + (size_t)((cc) * 32 + br + 16) * 256 + bseg * 8); \
} while (0)

    K_ISSUE(0, 0); CP_COMMIT();
    K_ISSUE(1, 1); CP_COMMIT();
    K_ISSUE(2, 2); CP_COMMIT();

    uint32_t a_lm = (uint32_t)(warp_m * 32 + (lane & 15)) * 80 + (lane >> 4) * 16;
    uint32_t b_k = (uint32_t)(lane & 15) * 144;
    uint32_t b_c = (uint32_t)(warp_n * 32 + (lane >> 4) * 8) * 2;

    for (int c = 0; c < NC; c++) {
        CP_WAIT2();
        __syncthreads();
        if (c + 3 < NC) K_ISSUE(c + 3, (c + 3) & 3);
        CP_COMMIT();
        uint32_t ab = sbase + (c & 3) * K_STG, bbf = ab + K_ABY;
#pragma unroll
        for (int k16 = 0; k16 < 2; k16++) {
            uint32_t af[2][4];
            uint32_t bf[4][2];
#pragma unroll
            for (int mt = 0; mt < 2; mt++)
                ldmat_x4(af[mt][0], af[mt][1], af[mt][2], af[mt][3],
                         ab + a_lm + mt * 16 * 80 + k16 * 32);
#pragma unroll
            for (int bt = 0; bt < 2; bt++) {
                uint32_t addr = bbf + b_k + (uint32_t)(k16 * 16) * 144 + b_c + bt * 32;
                uint32_t r0, r1, r2, r3;
                ldmat_x4_t(r0, r1, r2, r3, addr);
                bf[2 * bt + 0][0] = r0; bf[2 * bt + 0][1] = r1;
                bf[2 * bt + 1][0] = r2; bf[2 * bt + 1][1] = r3;
            }
#pragma unroll
            for (int mt = 0; mt < 2; mt++)
#pragma unroll
                for (int nt = 0; nt < 4; nt++)
                    mma_bf16(acc[mt][nt], af[mt], bf[nt]);
        }
    }
#undef K_ISSUE

    float* outp = kp + (size_t)z * NP * (SA * DKK);
#pragma unroll
    for (int mt = 0; mt < 2; mt++) {
        int row = m0 + warp_m * 32 + mt * 16 + (lane >> 2);
        float* c0 = outp + (size_t)row * 256;
        float* c1 = outp + (size_t)(row + 8) * 256;
#pragma unroll
        for (int nt = 0; nt < 4; nt++) {
            int col = n0 + warp_n * 32 + nt * 8 + (lane & 3) * 2;
            *(float2*)(c0 + col) = make_float2(acc[mt][nt][0], acc[mt][nt][1]);
            *(float2*)(c1 + col) = make_float2(acc[mt][nt][2], acc[mt][nt][3]);
        }
    }
}

// ---------------- reduce partials -> keys output + normalized keys ----------------
__global__ void knorm_kernel(const float* __restrict__ kp, float* __restrict__ keys,
                             float* __restrict__ kn)
{
    int n = blockIdx.x, a = blockIdx.y, tid = threadIdx.x;  // 64 threads
    size_t idx = (size_t)n * (SA * DKK) + a * DKK + tid;
    float v = 0.0f;
#pragma unroll
    for (int ks = 0; ks < KZ; ks++) v += kp[(size_t)ks * NP * (SA * DKK) + idx];
    keys[idx] = v;
    float ss = v * v;
#pragma unroll
    for (int o = 16; o; o >>= 1) ss += __shfl_xor_sync(0xffffffffu, ss, o);
    __shared__ float r2[2];
    if ((tid & 31) == 0) r2[tid >> 5] = ss;
    __syncthreads();
    float nrm = sqrtf(r2[0] + r2[1]);
    kn[idx] = v / (nrm + 1e-8f);
}

// ---------------- queries ----------------
__global__ void q_kernel(const float* __restrict__ hA, const float* __restrict__ WQ,
                         const float* __restrict__ logits, float* __restrict__ qw)
{
    int b = blockIdx.x, a = blockIdx.y, tid = threadIdx.x;  // 64 threads
    __shared__ float hs[DA];
    for (int i = tid; i < DA; i += 64) hs[i] = hA[(size_t)b * DA + i];
    __syncthreads();
    float q = 0.0f;
    const float* w = WQ + (size_t)a * DA * DKK + tid;
#pragma unroll 4
    for (int d = 0; d < DA; d++) q += hs[d] * w[(size_t)d * DKK];
    float ss = q * q;
#pragma unroll
    for (int o = 16; o; o >>= 1) ss += __shfl_xor_sync(0xffffffffu, ss, o);
    __shared__ float r2[2];
    if ((tid & 31) == 0) r2[tid >> 5] = ss;
    __syncthreads();
    float nrm = sqrtf(r2[0] + r2[1]);
    float l0 = logits[0], l1 = logits[1], l2 = logits[2], l3 = logits[3];
    float m = fmaxf(fmaxf(l0, l1), fmaxf(l2, l3));
    float e0 = expf(l0 - m), e1 = expf(l1 - m), e2 = expf(l2 - m), e3 = expf(l3 - m);
    float ea = (a == 0) ? e0 : (a == 1) ? e1 : (a == 2) ? e2 : e3;
    float wa = ea / (e0 + e1 + e2 + e3);
    qw[(size_t)b * (SA * DKK) + a * DKK + tid] = wa * q / (nrm + 1e-8f);
}

// ---------------- scores + gate/exp -> alpha_raw ----------------
__global__ void scores_kernel(const float* __restrict__ QW, const float* __restrict__ KN,
                              const float* __restrict__ tau_p, float* __restrict__ alpha)
{
    int n0 = blockIdx.x * 64, m0 = blockIdx.y * 64;
    __shared__ float As[16][64];
    __shared__ float Bs[16][64];
    int tid = threadIdx.x;
    int am = tid >> 2, ak = (tid & 3) * 4;
    int bn = tid >> 2, bk = (tid & 3) * 4;
    int ty = tid >> 4, tx = tid & 15;
    float acc[4][4] = {};
    for (int k0 = 0; k0 < 256; k0 += 16) {
        float4 av = *(const float4*)(QW + (size_t)(m0 + am) * 256 + k0 + ak);
        As[ak + 0][am] = av.x; As[ak + 1][am] = av.y; As[ak + 2][am] = av.z; As[ak + 3][am] = av.w;
        float4 bv = *(const float4*)(KN + (size_t)(n0 + bn) * 256 + k0 + bk);
        Bs[bk + 0][bn] = bv.x; Bs[bk + 1][bn] = bv.y; Bs[bk + 2][bn] = bv.z; Bs[bk + 3][bn] = bv.w;
        __syncthreads();
#pragma unroll
        for (int kk = 0; kk < 16; kk++) {
            float ar[4], br[4];
            *(float4*)ar = *(const float4*)&As[kk][ty * 4];
            *(float4*)br = *(const float4*)&Bs[kk][tx * 4];
#pragma unroll
            for (int i = 0; i < 4; i++)
#pragma unroll
                for (int j = 0; j < 4; j++) acc[i][j] += ar[i] * br[j];
        }
        __syncthreads();
    }
    float tau = tau_p[0];
#pragma unroll
    for (int i = 0; i < 4; i++)
#pragma unroll
        for (int j = 0; j < 4; j++) {
            float s = acc[i][j];
            float g = 1.0f / (1.0f + expf(-(s - tau)));
            alpha[(size_t)(m0 + ty * 4 + i) * NP + n0 + tx * 4 + j] = g * expf(s);
        }
}

// ---------------- alpha row normalization (+ bf16 copy) ----------------
__global__ void alpha_norm_kernel(float* __restrict__ alpha, __nv_bfloat16* __restrict__ ab)
{
    int b = blockIdx.x, tid = threadIdx.x;  // 256 threads
    float* row = alpha + (size_t)b * NP;
    __nv_bfloat16* rowb = ab + (size_t)b * NP;
    float loc[8]; float s = 0.0f;
#pragma unroll
    for (int i = 0; i < 8; i++) { loc[i] = row[tid + 256 * i]; s += loc[i]; }
#pragma unroll
    for (int o = 16; o; o >>= 1) s += __shfl_xor_sync(0xffffffffu, s, o);
    __shared__ float red[8];
    if ((tid & 31) == 0) red[tid >> 5] = s;
    __syncthreads();
    float tot = 0.0f;
#pragma unroll
    for (int i = 0; i < 8; i++) tot += red[i];
    float inv = 1.0f / (tot + 1e-8f);
#pragma unroll
    for (int i = 0; i < 8; i++) {
        float v = loc[i] * inv;
        row[tid + 256 * i] = v;
        rowb[tid + 256 * i] = __float2bfloat16(v);
    }
}

// ---------------- FUSED: BIG GEMM v4 (blocks 0..1023) + bdelta split-K (blocks 1024..1151) ----------------
#define B4_ABY (256 * 80)   // 20480 B per A stage
#define B4_BBY (32 * 144)   // 4608 B per B stage
#define B4_STG (B4_ABY + B4_BBY)
#define B4_SMEM (2 * B4_STG)   // 50176 B (dynamic)

__global__ void __launch_bounds__(256, 2) big_mma_kernel(
    const __nv_bfloat16* __restrict__ Ab, const __nv_bfloat16* __restrict__ Bb,
    const float* __restrict__ Wbase, float* __restrict__ C,
    const float* __restrict__ alpha, const float* __restrict__ pool,
    float* __restrict__ bt)
{
    extern __shared__ __align__(16) char dsm[];
    int tid = threadIdx.x, lane = tid & 31, wid = tid >> 5;

    if (blockIdx.x >= 1024) {
        // ---------------- bdelta branch ----------------
        int id = blockIdx.x - 1024;          // 0..127, orig grid (x=4, y=4, z=8)
        int bx = id & 3, by = (id >> 2) & 3, z = id >> 4;
        int m0 = by * 64, n0 = bx * 64;
        int kbeg = z * BDK;
        float* As = (float*)dsm;             // [16][64]
        float* Bs = As + 16 * 64;            // [16][64]
        int am = tid >> 2, ak = (tid & 3) * 4;
        int bk = tid >> 4, bn = (tid & 15) * 4;
        int ty = tid >> 4, tx = tid & 15;
        float acc[4][4] = {};
        const float* Ap = alpha + (size_t)(m0 + am) * NP + kbeg + ak;
        const float* Bp = pool + 4096 + (size_t)(kbeg + bk) * DP + n0 + bn;
        float4 av = *(const float4*)Ap;
        float4 bv = *(const float4*)Bp;
        for (int k0 = 0; k0 < BDK; k0 += 16) {
            As[(ak + 0) * 64 + am] = av.x; As[(ak + 1) * 64 + am] = av.y;
            As[(ak + 2) * 64 + am] = av.z; As[(ak + 3) * 64 + am] = av.w;
            *(float4*)&Bs[bk * 64 + bn] = bv;
            __syncthreads();
            if (k0 + 16 < BDK) {
                av = *(const float4*)(Ap + (k0 + 16));
                bv = *(const float4*)(Bp + (size_t)(k0 + 16) * DP);
            }
#pragma unroll
            for (int kk = 0; kk < 16; kk++) {
                float ar[4], br[4];
                *(float4*)ar = *(const float4*)&As[kk * 64 + ty * 4];
                *(float4*)br = *(const float4*)&Bs[kk * 64 + tx * 4];
#pragma unroll
                for (int i = 0; i < 4; i++)
#pragma unroll
                    for (int j = 0; j < 4; j++) acc[i][j] += ar[i] * br[j];
            }
            __syncthreads();
        }
        float* outp = bt + (size_t)z * BATCH * DB;
#pragma unroll
        for (int i = 0; i < 4; i++)
#pragma unroll
            for (int j = 0; j < 4; j++)
                outp[(size_t)(m0 + ty * 4 + i) * DB + n0 + tx * 4 + j] = acc[i][j];
        return;
    }

    // ---------------- big GEMM branch ----------------
    int warp_m = wid;                 // 0..7, rows warp_m*32 .. +31
    int n0 = blockIdx.x * 64;

    uint32_t sa = smem_u32(dsm);

    int ar = tid >> 2, aseg = tid & 3;     // A: rows ar+{0,64,128,192}, 4 segs
    int br = tid >> 3, bseg = tid & 7;     // B: 32 rows x 8 segs of 16B
    const __nv_bfloat16* Agb = Ab;
    const __nv_bfloat16* Bgb = Bb + n0;

    float acc[2][8][4];
#pragma unroll
    for (int i = 0; i < 2; i++)
#pragma unroll
        for (int j = 0; j < 8; j++)
#pragma unroll
            for (int q = 0; q < 4; q++) acc[i][j][q] = 0.0f;

    const int NC = NP / 32;   // 64
#define B_ISSUE(cc, ss) do { \
    uint32_t ab = sa + (ss) * B4_STG, bbf = ab + B4_ABY; \
    cpa16(ab + (uint32_t)ar * 80 + aseg * 16, Agb + (size_t)ar * NP + (cc) * 32 + aseg * 8); \
    cpa16(ab + (uint32_t)(ar + 64) * 80 + aseg * 16, Agb + (size_t)(ar + 64) * NP + (cc) * 32 + aseg * 8); \
    cpa16(ab + (uint32_t)(ar + 128) * 80 + aseg * 16, Agb + (size_t)(ar + 128) * NP + (cc) * 32 + aseg * 8); \
    cpa16(ab + (uint32_t)(ar + 192) * 80 + aseg * 16, Agb + (size_t)(ar + 192) * NP + (cc) * 32 + aseg * 8); \
    cpa16(bbf + (uint32_t)br * 144 + bseg * 16, Bgb + (size_t)((cc) * 32 + br) * NDE + bseg * 8); \
} while (0)

    B_ISSUE(0, 0); CP_COMMIT();
    B_ISSUE(1, 1); CP_COMMIT();
    CP_WAIT1(); __syncthreads();

    uint32_t a_lm = (uint32_t)(warp_m * 32 + (lane & 15)) * 80 + (lane >> 4) * 16;
    uint32_t b_k = (uint32_t)(lane & 15) * 144;
    uint32_t b_c = (uint32_t)(lane >> 4) * 16;

    for (int c = 0; c < NC; c++) {
        int buf = c & 1;
        uint32_t ab = sa + buf * B4_STG, bbf = ab + B4_ABY;
#pragma unroll
        for (int k16 = 0; k16 < 2; k16++) {
            uint32_t af[2][4];
            uint32_t bf[8][2];
#pragma unroll
            for (int mt = 0; mt < 2; mt++)
                ldmat_x4(af[mt][0], af[mt][1], af[mt][2], af[mt][3],
                         ab + a_lm + mt * 16 * 80 + k16 * 32);
#pragma unroll
            for (int bt2 = 0; bt2 < 4; bt2++) {
                uint32_t addr = bbf + b_k + (uint32_t)(k16 * 16) * 144 + b_c + bt2 * 32;
                uint32_t r0, r1, r2, r3;
                ldmat_x4_t(r0, r1, r2, r3, addr);
                bf[2 * bt2 + 0][0] = r0; bf[2 * bt2 + 0][1] = r1;
                bf[2 * bt2 + 1][0] = r2; bf[2 * bt2 + 1][1] = r3;
            }
#pragma unroll
            for (int mt = 0; mt < 2; mt++)
#pragma unroll
                for (int nt = 0; nt < 8; nt++)
                    mma_bf16(acc[mt][nt], af[mt], bf[nt]);
        }
        __syncthreads();
        if (c + 2 < NC) B_ISSUE(c + 2, buf);
        CP_COMMIT();
        CP_WAIT1();
        __syncthreads();
    }
#undef B_ISSUE

#pragma unroll
    for (int mt = 0; mt < 2; mt++) {
        int row = warp_m * 32 + mt * 16 + (lane >> 2);
        float* c0 = C + (size_t)row * NDE + n0;
        float* c1 = C + (size_t)(row + 8) * NDE + n0;
        const float* wb = Wbase + n0;
#pragma unroll
        for (int nt = 0; nt < 8; nt++) {
            int col = nt * 8 + (lane & 3) * 2;
            float2 w2 = *(const float2*)(wb + col);
            float2 o0, o1;
            o0.x = acc[mt][nt][0] + w2.x; o0.y = acc[mt][nt][1] + w2.y;
            o1.x = acc[mt][nt][2] + w2.x; o1.y = acc[mt][nt][3] + w2.y;
            *(float2*)(c0 + col) = o0;
            *(float2*)(c1 + col) = o1;
        }
    }
}

// ---------------- h_t + residual + LayerNorm (sums b_delta partials) ----------------
__global__ void ht_ln_kernel(const float* __restrict__ Wout, const float* __restrict__ hA,
                             const float* __restrict__ bparts, const float* __restrict__ b_base,
                             const float* __restrict__ gamma_p, const float* __restrict__ ln_s,
                             const float* __restrict__ ln_b, float* __restrict__ hmid)
{
    int b = blockIdx.x, tid = threadIdx.x;     // 256 threads
    int lane = tid & 31, warp = tid >> 5;
    __shared__ float hs[DA];
    __shared__ float ys[DA];
    __shared__ float bsum[DB];
    hs[tid] = hA[(size_t)b * DA + tid];
    {
        float bs = 0.0f;
#pragma unroll
        for (int ks = 0; ks < BDS; ks++)
            bs += bparts[(size_t)ks * BATCH * DB + (size_t)b * DB + tid];
        bsum[tid] = bs;
    }
    __syncthreads();
    float gamma = gamma_p[0];
    const float* Wb = Wout + (size_t)b * NDE;
    for (int c = warp; c < DB; c += 8) {
        const float* row = Wb + (size_t)c * DA;
        float s = 0.0f;
#pragma unroll
        for (int i = 0; i < 8; i++) { int a = lane + 32 * i; s += row[a] * hs[a]; }
#pragma unroll
        for (int o = 16; o; o >>= 1) s += __shfl_xor_sync(0xffffffffu, s, o);
        if (lane == 0) {
            float htv = s + bsum[c] + b_base[c];
            ys[c] = hs[c] + gamma * htv;
        }
    }
    __syncthreads();
    float v = ys[tid];
    float s1 = v, s2 = v * v;
#pragma unroll
    for (int o = 16; o; o >>= 1) {
        s1 += __shfl_xor_sync(0xffffffffu, s1, o);
        s2 += __shfl_xor_sync(0xffffffffu, s2, o);
    }
    __shared__ float red[18];
    if (lane == 0) { red[warp] = s1; red[8 + warp] = s2; }
    __syncthreads();
    if (tid == 0) {
        float a = 0.0f, q = 0.0f;
#pragma unroll
        for (int i = 0; i < 8; i++) { a += red[i]; q += red[8 + i]; }
        red[16] = a / (float)DA;
        red[17] = q / (float)DA;
    }
    __syncthreads();
    float mu = red[16];
    float var = fmaxf(red[17] - mu * mu, 0.0f);
    float r = rsqrtf(var + 1e-6f);
    hmid[(size_t)b * DA + tid] = (v - mu) * r * ln_s[tid] + ln_b[tid];
}

// ---------------- launch ----------------
extern "C" void kernel_launch(void* const* d_in, const int* in_sizes, int n_in,
                              void* d_out, int out_size)
{
    const float* x      = (const float*)d_in[0];
    const float* pool   = (const float*)d_in[1];
    const float* A_w0   = (const float*)d_in[2];
    const float* A_b0   = (const float*)d_in[3];
    const float* A_w1   = (const float*)d_in[4];
    const float* A_b1   = (const float*)d_in[5];
    const float* W_Q    = (const float*)d_in[6];
    const float* W_K    = (const float*)d_in[7];
    const float* logits = (const float*)d_in[8];
    const float* tau    = (const float*)d_in[9];
    const float* W_base = (const float*)d_in[10];
    const float* b_base = (const float*)d_in[11];
    const float* gamma  = (const float*)d_in[12];
    const float* ln_s   = (const float*)d_in[13];
    const float* ln_b   = (const float*)d_in[14];
    const float* B_w0   = (const float*)d_in[15];
    const float* B_b0   = (const float*)d_in[16];
    const float* B_w1   = (const float*)d_in[17];
    const float* B_b1   = (const float*)d_in[18];

    float* out       = (float*)d_out;
    float* out_alpha = out + OUT_ALPHA;
    float* out_W     = out + OUT_W;
    float* out_keys  = out + OUT_KEYS;

    float *p_hid, *p_hA, *p_qw, *p_kn, *p_bt, *p_hmid, *p_hid2, *p_kp;
    __nv_bfloat16 *p_ab, *p_UVb, *p_px, *p_wx;
    cudaGetSymbolAddress((void**)&p_hid,  g_hid);
    cudaGetSymbolAddress((void**)&p_hA,   g_hA);
    cudaGetSymbolAddress((void**)&p_qw,   g_qw);
    cudaGetSymbolAddress((void**)&p_kn,   g_kn);
    cudaGetSymbolAddress((void**)&p_bt,   g_bt);
    cudaGetSymbolAddress((void**)&p_hmid, g_hmid);
    cudaGetSymbolAddress((void**)&p_hid2, g_hid2);
    cudaGetSymbolAddress((void**)&p_kp,   g_kp);
    cudaGetSymbolAddress((void**)&p_ab,   g_alphab);
    cudaGetSymbolAddress((void**)&p_UVb,  g_UVb);
    cudaGetSymbolAddress((void**)&p_px,   g_poolx);
    cudaGetSymbolAddress((void**)&p_wx,   g_wkx);

    cudaFuncSetAttribute(big_mma_kernel, cudaFuncAttributeMaxDynamicSharedMemorySize, B4_SMEM);

    // 1-2) hi/lo expansions
    expand_pool_kernel<<<NP, 256>>>(pool, p_px);
    expand_wk_kernel<<<KEXP, 256>>>(W_K, p_wx);
    // 3) first MLP gemm (independent -> fused keys+uv is launch #4, profiled)
    gemm64<1><<<dim3(HIDN / 64, BATCH / 64), 256>>>(x, A_w0, A_b0, p_hid, DMODEL, DMODEL, HIDN, HIDN);
    // 4) FUSED keys split-bf16 mma (1024 blocks) + UV build (2048 blocks)
    keys_uv_kernel<<<3072, 128>>>(p_px, p_wx, p_kp, pool, p_UVb);
    // 5) reduce + keys output + k_norm
    knorm_kernel<<<dim3(NP, SA), 64>>>(p_kp, out_keys, p_kn);
    // 6-7) h_A MLP second gemm + queries
    gemm64<0><<<dim3(DA / 64, BATCH / 64), 256>>>(p_hid, A_w1, A_b1, p_hA, HIDN, HIDN, DA, DA);
    q_kernel<<<dim3(BATCH, SA), 64>>>(p_hA, W_Q, logits, p_qw);
    // 8-9) scores -> alpha
    scores_kernel<<<dim3(NP / 64, BATCH / 64), 256>>>(p_qw, p_kn, tau, out_alpha);
    alpha_norm_kernel<<<BATCH, 256>>>(out_alpha, p_ab);
    // 10) FUSED big GEMM (1024 blocks) + bdelta split-K (128 blocks)
    big_mma_kernel<<<1152, 256, B4_SMEM>>>(p_ab, p_UVb, W_base, out_W, out_alpha, pool, p_bt);
    // 11) h_t, residual, layernorm (sums bdelta partials)
    ht_ln_kernel<<<BATCH, 256>>>(out_W, p_hA, p_bt, b_base, gamma, ln_s, ln_b, p_hmid);
    // 12-13) output MLP
    gemm64<1><<<dim3(HIDN / 64, BATCH / 64), 256>>>(p_hmid, B_w0, B_b0, p_hid2, DA, DA, HIDN, HIDN);
    gemm64<0><<<dim3(DMODEL / 64, BATCH / 64), 256>>>(p_hid2, B_w1, B_b1, out, HIDN, HIDN, DMODEL, DMODEL);
}

// round 16
// speedup vs baseline: 1.0617x; 1.0235x over previous
#include <cuda_runtime.h>
#include <cuda_bf16.h>
#include <cstdint>
#include <cstddef>

// ---------------- problem constants ----------------
#define BATCH  256
#define DMODEL 512
#define DA     256
#define DB     256
#define RR     8
#define NP     2048
#define DP     4608
#define SA     4
#define DKK    64
#define HIDN   1024
#define NDE    65536           // DB*DA
#define KEXP   13824           // 3*DP (hi | lo | hi)
#define KZ     8               // keys split-K
#define KZLEN  (KEXP / KZ)     // 1728
#define BDS    8               // b_delta split-K
#define BDK    (NP / BDS)      // 256

// output layout (flattened tuple: output, alpha, W_assembled, keys)
#define OUT_ALPHA  (BATCH*DMODEL)
#define OUT_W      (OUT_ALPHA + BATCH*NP)
#define OUT_KEYS   (OUT_W + (size_t)BATCH*DB*DA)

// ---------------- scratch (device globals; no allocation allowed) ----------------
__device__ float g_hid [BATCH*HIDN];
__device__ float g_hA  [BATCH*DA];
__device__ float g_qw  [BATCH*SA*DKK];
__device__ float g_kn  [NP*SA*DKK];
__device__ float g_bt  [BDS*BATCH*DB];                  // b_delta split-K partials (2MB)
__device__ float g_hmid[BATCH*DA];
__device__ float g_hid2[BATCH*HIDN];
__device__ float g_kp  [KZ*NP*SA*DKK];                  // keys split-K partials (16MB)
__device__ __nv_bfloat16 g_alphab[BATCH*NP];            // alpha in bf16
__device__ __nv_bfloat16 g_UVb[(size_t)NP*NDE];         // UV in bf16 (268MB)
__device__ __nv_bfloat16 g_poolx[(size_t)NP*KEXP];      // pool hi/lo expanded (56.6MB)
__device__ __nv_bfloat16 g_wkx[(size_t)KEXP*256];       // W_K hi/lo expanded (7MB)

// ---------------- helpers ----------------
__device__ __forceinline__ float gelu_f(float x) {
    const float c = 0.7978845608028654f;
    return 0.5f * x * (1.0f + tanhf(c * (x + 0.044715f * x * x * x)));
}
__device__ __forceinline__ uint32_t smem_u32(const void* p) {
    uint32_t a;
    asm("{ .reg .u64 t; cvta.to.shared.u64 t, %1; cvt.u32.u64 %0, t; }" : "=r"(a) : "l"(p));
    return a;
}
__device__ __forceinline__ void ldmat_x4(uint32_t& r0, uint32_t& r1, uint32_t& r2, uint32_t& r3,
                                         uint32_t addr) {
    asm volatile("ldmatrix.sync.aligned.m8n8.x4.shared.b16 {%0,%1,%2,%3}, [%4];"
                 : "=r"(r0), "=r"(r1), "=r"(r2), "=r"(r3) : "r"(addr));
}
__device__ __forceinline__ void ldmat_x4_t(uint32_t& r0, uint32_t& r1, uint32_t& r2, uint32_t& r3,
                                           uint32_t addr) {
    asm volatile("ldmatrix.sync.aligned.m8n8.x4.trans.shared.b16 {%0,%1,%2,%3}, [%4];"
                 : "=r"(r0), "=r"(r1), "=r"(r2), "=r"(r3) : "r"(addr));
}
__device__ __forceinline__ void mma_bf16(float* d, const uint32_t* a, const uint32_t* b) {
    asm volatile("mma.sync.aligned.m16n8k16.row.col.f32.bf16.bf16.f32 "
                 "{%0,%1,%2,%3}, {%4,%5,%6,%7}, {%8,%9}, {%0,%1,%2,%3};"
                 : "+f"(d[0]), "+f"(d[1]), "+f"(d[2]), "+f"(d[3])
                 : "r"(a[0]), "r"(a[1]), "r"(a[2]), "r"(a[3]), "r"(b[0]), "r"(b[1]));
}
__device__ __forceinline__ void cpa16(uint32_t dst, const void* src) {
    asm volatile("cp.async.cg.shared.global [%0], [%1], 16;" :: "r"(dst), "l"(src));
}
#define CP_COMMIT() asm volatile("cp.async.commit_group;" ::: "memory")
#define CP_WAIT1()  asm volatile("cp.async.wait_group 1;" ::: "memory")
#define CP_WAIT2()  asm volatile("cp.async.wait_group 2;" ::: "memory")

// packed f32x2 fma (proven at compute_103 in round-1 kernel)
__device__ __forceinline__ unsigned long long dupf2(float a) {
    unsigned long long r; unsigned int u = __float_as_uint(a);
    asm("mov.b64 %0, {%1, %1};" : "=l"(r) : "r"(u));
    return r;
}
__device__ __forceinline__ unsigned long long packf2(float lo, float hi) {
    unsigned long long r;
    asm("mov.b64 %0, {%1, %2};" : "=l"(r) : "r"(__float_as_uint(lo)), "r"(__float_as_uint(hi)));
    return r;
}
__device__ __forceinline__ void fma2(unsigned long long& d, unsigned long long a, unsigned long long b) {
    asm("fma.rn.f32x2 %0, %1, %2, %0;" : "+l"(d) : "l"(a), "l"(b));
}
__device__ __forceinline__ float2 unpkf2(unsigned long long v) {
    unsigned int lo, hi;
    asm("mov.b64 {%0, %1}, %2;" : "=r"(lo), "=r"(hi) : "l"(v));
    return make_float2(__uint_as_float(lo), __uint_as_float(hi));
}

// ---------------- generic 64x64x16 SGEMM (small MLPs) ----------------
template <int ACT>
__global__ void gemm64(const float* __restrict__ A, const float* __restrict__ B,
                       const float* __restrict__ bias, float* __restrict__ C,
                       int K, int lda, int ldb, int ldc)
{
    __shared__ float As[16][64];
    __shared__ float Bs[16][64];
    int tid = threadIdx.x;
    int m0 = blockIdx.y * 64, n0 = blockIdx.x * 64;
    int am = tid >> 2, ak = (tid & 3) * 4;
    int bk = tid >> 4, bn = (tid & 15) * 4;
    int ty = tid >> 4, tx = tid & 15;
    float acc[4][4] = {};
    const float* Ap = A + (size_t)(m0 + am) * lda + ak;
    const float* Bp = B + (size_t)bk * ldb + n0 + bn;
    float4 av = *(const float4*)Ap;
    float4 bv = *(const float4*)Bp;
    for (int k0 = 0; k0 < K; k0 += 16) {
        As[ak + 0][am] = av.x; As[ak + 1][am] = av.y; As[ak + 2][am] = av.z; As[ak + 3][am] = av.w;
        *(float4*)&Bs[bk][bn] = bv;
        __syncthreads();
        if (k0 + 16 < K) {
            av = *(const float4*)(Ap + (k0 + 16));
            bv = *(const float4*)(Bp + (size_t)(k0 + 16) * ldb);
        }
#pragma unroll
        for (int kk = 0; kk < 16; kk++) {
            float ar[4], br[4];
            *(float4*)ar = *(const float4*)&As[kk][ty * 4];
            *(float4*)br = *(const float4*)&Bs[kk][tx * 4];
#pragma unroll
            for (int i = 0; i < 4; i++)
#pragma unroll
                for (int j = 0; j < 4; j++) acc[i][j] += ar[i] * br[j];
        }
        __syncthreads();
    }
#pragma unroll
    for (int i = 0; i < 4; i++) {
        int m = m0 + ty * 4 + i;
#pragma unroll
        for (int j = 0; j < 4; j++) {
            int n = n0 + tx * 4 + j;
            float c = acc[i][j];
            if (bias) c += bias[n];
            if (ACT == 1) c = gelu_f(c);
            C[(size_t)m * ldc + n] = c;
        }
    }
}

// ---------------- hi/lo expansion: pool -> poolx [n][hi|lo|hi] ----------------
__global__ void expand_pool_kernel(const float* __restrict__ pool, __nv_bfloat16* __restrict__ px)
{
    int n = blockIdx.x, tid = threadIdx.x;
    const float* src = pool + (size_t)n * DP;
    __nv_bfloat16* dst = px + (size_t)n * KEXP;
#pragma unroll 2
    for (int p = tid; p < DP; p += 256) {
        float x = src[p];
        __nv_bfloat16 hi = __float2bfloat16(x);
        __nv_bfloat16 lo = __float2bfloat16(x - __bfloat162float(hi));
        dst[p] = hi;
        dst[DP + p] = lo;
        dst[2 * DP + p] = hi;
    }
}

// ---------------- hi/lo expansion: W_K -> wkx [k][c], c=a*64+q ----------------
__global__ void expand_wk_kernel(const float* __restrict__ WK, __nv_bfloat16* __restrict__ wx)
{
    int k = blockIdx.x, c = threadIdx.x;   // 13824 blocks x 256 threads
    int s = k / DP, p = k % DP;
    int a = c >> 6, q = c & 63;
    float x = WK[(size_t)a * DP * DKK + (size_t)p * DKK + q];
    __nv_bfloat16 hi = __float2bfloat16(x);
    __nv_bfloat16 v;
    if (s < 2) v = hi;
    else v = __float2bfloat16(x - __bfloat162float(hi));
    wx[(size_t)k * 256 + c] = v;
}

// ---------------- FUSED: keys mma (blocks 0..1023) + UV build (blocks 1024..3071) ----------------
// keys: BM=64, BN=64, BK=32, 128 threads (2m x 2n warps), KZ=8 split-K, 4-stage ring.
// uv:   n = bid-1024; 128 threads, 2 columns/thread via packed fma.rn.f32x2.
#define K_ABY (64 * 80)     // 5120 B
#define K_BBY (32 * 144)    // 4608 B
#define K_STG (K_ABY + K_BBY)

__global__ void __launch_bounds__(128, 4) keys_uv_kernel(
    const __nv_bfloat16* __restrict__ Ax, const __nv_bfloat16* __restrict__ Bx,
    float* __restrict__ kp, const float* __restrict__ pool, __nv_bfloat16* __restrict__ UV)
{
    __shared__ __align__(16) char smem[4 * K_STG];   // 38912 B (uv uses first 8KB as float)
    int tid = threadIdx.x;
    int bid = blockIdx.x;

    if (bid >= 1024) {
        // ---------------- UV branch (f32x2 packed) ----------------
        int n = bid - 1024;
        float* Us = (float*)smem;                     // 2048 floats
        const float* p = pool + (size_t)n * DP;
        for (int i = tid; i < DB * RR; i += 128) Us[i] = p[i];
        unsigned long long vv[RR];
#pragma unroll
        for (int r = 0; r < RR; r++)
            vv[r] = packf2(p[2048 + r * 256 + tid], p[2048 + r * 256 + tid + 128]);
        __syncthreads();
        __nv_bfloat16* out = UV + (size_t)n * NDE;
#pragma unroll 2
        for (int d = 0; d < DB; d++) {
            unsigned long long acc2 = 0ULL;
#pragma unroll
            for (int r = 0; r < RR; r++)
                fma2(acc2, dupf2(Us[d * RR + r]), vv[r]);
            float2 a = unpkf2(acc2);
            out[(size_t)d * 256 + tid] = __float2bfloat16(a.x);
            out[(size_t)d * 256 + tid + 128] = __float2bfloat16(a.y);
        }
        return;
    }

    // ---------------- keys branch ----------------
    int lane = tid & 31, wid = tid >> 5;
    int warp_m = wid & 1, warp_n = wid >> 1;
    int bx = bid & 3, by = (bid >> 2) & 31, z = bid >> 7;
    int n0 = bx * 64;
    int m0 = by * 64;
    int kbase = z * KZLEN;

    uint32_t sbase = smem_u32(smem);
    int ar = tid >> 2, aseg = tid & 3;
    int br = tid >> 3, bseg = tid & 7;
    const __nv_bfloat16* Agb = Ax + (size_t)m0 * KEXP + kbase;
    const __nv_bfloat16* Bgb = Bx + (size_t)kbase * 256 + n0;

    float acc[2][4][4];
#pragma unroll
    for (int i = 0; i < 2; i++)
#pragma unroll
        for (int j = 0; j < 4; j++)
#pragma unroll
            for (int q = 0; q < 4; q++) acc[i][j][q] = 0.0f;

    const int NC = KZLEN / 32;   // 54
#define K_ISSUE(cc, ss) do { \
    uint32_t ab = sbase + (ss) * K_STG, bbf = ab + K_ABY; \
    cpa16(ab + (uint32_t)ar * 80 + aseg * 16, Agb + (size_t)ar * KEXP + (cc) * 32 + aseg * 8); \
    cpa16(ab + (uint32_t)(ar + 32) * 80 + aseg * 16, Agb + (size_t)(ar + 32) * KEXP + (cc) * 32 + aseg * 8); \
    cpa16(bbf + (uint32_t)br * 144 + bseg * 16, Bgb + (size_t)((cc) * 32 + br) * 256 + bseg * 8); \
    cpa16(bbf + (uint32_t)(br + 16) * 144 + bseg * 16, Bgb + (size_t)((cc) * 32 + br + 16) * 256 + bseg * 8); \
} while (0)

    K_ISSUE(0, 0); CP_COMMIT();
    K_ISSUE(1, 1); CP_COMMIT();
    K_ISSUE(2, 2); CP_COMMIT();

    uint32_t a_lm = (uint32_t)(warp_m * 32 + (lane & 15)) * 80 + (lane >> 4) * 16;
    uint32_t b_k = (uint32_t)(lane & 15) * 144;
    uint32_t b_c = (uint32_t)(warp_n * 32 + (lane >> 4) * 8) * 2;

    for (int c = 0; c < NC; c++) {
        CP_WAIT2();
        __syncthreads();
        if (c + 3 < NC) K_ISSUE(c + 3, (c + 3) & 3);
        CP_COMMIT();
        uint32_t ab = sbase + (c & 3) * K_STG, bbf = ab + K_ABY;
#pragma unroll
        for (int k16 = 0; k16 < 2; k16++) {
            uint32_t af[2][4];
            uint32_t bf[4][2];
#pragma unroll
            for (int mt = 0; mt < 2; mt++)
                ldmat_x4(af[mt][0], af[mt][1], af[mt][2], af[mt][3],
                         ab + a_lm + mt * 16 * 80 + k16 * 32);
#pragma unroll
            for (int bt = 0; bt < 2; bt++) {
                uint32_t addr = bbf + b_k + (uint32_t)(k16 * 16) * 144 + b_c + bt * 32;
                uint32_t r0, r1, r2, r3;
                ldmat_x4_t(r0, r1, r2, r3, addr);
                bf[2 * bt + 0][0] = r0; bf[2 * bt + 0][1] = r1;
                bf[2 * bt + 1][0] = r2; bf[2 * bt + 1][1] = r3;
            }
#pragma unroll
            for (int mt = 0; mt < 2; mt++)
#pragma unroll
                for (int nt = 0; nt < 4; nt++)
                    mma_bf16(acc[mt][nt], af[mt], bf[nt]);
        }
    }
#undef K_ISSUE

    float* outp = kp + (size_t)z * NP * (SA * DKK);
#pragma unroll
    for (int mt = 0; mt < 2; mt++) {
        int row = m0 + warp_m * 32 + mt * 16 + (lane >> 2);
        float* c0 = outp + (size_t)row * 256;
        float* c1 = outp + (size_t)(row + 8) * 256;
#pragma unroll
        for (int nt = 0; nt < 4; nt++) {
            int col = n0 + warp_n * 32 + nt * 8 + (lane & 3) * 2;
            *(float2*)(c0 + col) = make_float2(acc[mt][nt][0], acc[mt][nt][1]);
            *(float2*)(c1 + col) = make_float2(acc[mt][nt][2], acc[mt][nt][3]);
        }
    }
}

// ---------------- reduce partials -> keys output + normalized keys ----------------
__global__ void knorm_kernel(const float* __restrict__ kp, float* __restrict__ keys,
                             float* __restrict__ kn)
{
    int n = blockIdx.x, a = blockIdx.y, tid = threadIdx.x;  // 64 threads
    size_t idx = (size_t)n * (SA * DKK) + a * DKK + tid;
    float v = 0.0f;
#pragma unroll
    for (int ks = 0; ks < KZ; ks++) v += kp[(size_t)ks * NP * (SA * DKK) + idx];
    keys[idx] = v;
    float ss = v * v;
#pragma unroll
    for (int o = 16; o; o >>= 1) ss += __shfl_xor_sync(0xffffffffu, ss, o);
    __shared__ float r2[2];
    if ((tid & 31) == 0) r2[tid >> 5] = ss;
    __syncthreads();
    float nrm = sqrtf(r2[0] + r2[1]);
    kn[idx] = v / (nrm + 1e-8f);
}

// ---------------- queries ----------------
__global__ void q_kernel(const float* __restrict__ hA, const float* __restrict__ WQ,
                         const float* __restrict__ logits, float* __restrict__ qw)
{
    int b = blockIdx.x, a = blockIdx.y, tid = threadIdx.x;  // 64 threads
    __shared__ float hs[DA];
    for (int i = tid; i < DA; i += 64) hs[i] = hA[(size_t)b * DA + i];
    __syncthreads();
    float q = 0.0f;
    const float* w = WQ + (size_t)a * DA * DKK + tid;
#pragma unroll 4
    for (int d = 0; d < DA; d++) q += hs[d] * w[(size_t)d * DKK];
    float ss = q * q;
#pragma unroll
    for (int o = 16; o; o >>= 1) ss += __shfl_xor_sync(0xffffffffu, ss, o);
    __shared__ float r2[2];
    if ((tid & 31) == 0) r2[tid >> 5] = ss;
    __syncthreads();
    float nrm = sqrtf(r2[0] + r2[1]);
    float l0 = logits[0], l1 = logits[1], l2 = logits[2], l3 = logits[3];
    float m = fmaxf(fmaxf(l0, l1), fmaxf(l2, l3));
    float e0 = expf(l0 - m), e1 = expf(l1 - m), e2 = expf(l2 - m), e3 = expf(l3 - m);
    float ea = (a == 0) ? e0 : (a == 1) ? e1 : (a == 2) ? e2 : e3;
    float wa = ea / (e0 + e1 + e2 + e3);
    qw[(size_t)b * (SA * DKK) + a * DKK + tid] = wa * q / (nrm + 1e-8f);
}

// ---------------- scores + gate/exp -> alpha_raw ----------------
__global__ void scores_kernel(const float* __restrict__ QW, const float* __restrict__ KN,
                              const float* __restrict__ tau_p, float* __restrict__ alpha)
{
    int n0 = blockIdx.x * 64, m0 = blockIdx.y * 64;
    __shared__ float As[16][64];
    __shared__ float Bs[16][64];
    int tid = threadIdx.x;
    int am = tid >> 2, ak = (tid & 3) * 4;
    int bn = tid >> 2, bk = (tid & 3) * 4;
    int ty = tid >> 4, tx = tid & 15;
    float acc[4][4] = {};
    for (int k0 = 0; k0 < 256; k0 += 16) {
        float4 av = *(const float4*)(QW + (size_t)(m0 + am) * 256 + k0 + ak);
        As[ak + 0][am] = av.x; As[ak + 1][am] = av.y; As[ak + 2][am] = av.z; As[ak + 3][am] = av.w;
        float4 bv = *(const float4*)(KN + (size_t)(n0 + bn) * 256 + k0 + bk);
        Bs[bk + 0][bn] = bv.x; Bs[bk + 1][bn] = bv.y; Bs[bk + 2][bn] = bv.z; Bs[bk + 3][bn] = bv.w;
        __syncthreads();
#pragma unroll
        for (int kk = 0; kk < 16; kk++) {
            float ar[4], br[4];
            *(float4*)ar = *(const float4*)&As[kk][ty * 4];
            *(float4*)br = *(const float4*)&Bs[kk][tx * 4];
#pragma unroll
            for (int i = 0; i < 4; i++)
#pragma unroll
                for (int j = 0; j < 4; j++) acc[i][j] += ar[i] * br[j];
        }
        __syncthreads();
    }
    float tau = tau_p[0];
#pragma unroll
    for (int i = 0; i < 4; i++)
#pragma unroll
        for (int j = 0; j < 4; j++) {
            float s = acc[i][j];
            float g = 1.0f / (1.0f + expf(-(s - tau)));
            alpha[(size_t)(m0 + ty * 4 + i) * NP + n0 + tx * 4 + j] = g * expf(s);
        }
}

// ---------------- alpha row normalization (+ bf16 copy) ----------------
__global__ void alpha_norm_kernel(float* __restrict__ alpha, __nv_bfloat16* __restrict__ ab)
{
    int b = blockIdx.x, tid = threadIdx.x;  // 256 threads
    float* row = alpha + (size_t)b * NP;
    __nv_bfloat16* rowb = ab + (size_t)b * NP;
    float loc[8]; float s = 0.0f;
#pragma unroll
    for (int i = 0; i < 8; i++) { loc[i] = row[tid + 256 * i]; s += loc[i]; }
#pragma unroll
    for (int o = 16; o; o >>= 1) s += __shfl_xor_sync(0xffffffffu, s, o);
    __shared__ float red[8];
    if ((tid & 31) == 0) red[tid >> 5] = s;
    __syncthreads();
    float tot = 0.0f;
#pragma unroll
    for (int i = 0; i < 8; i++) tot += red[i];
    float inv = 1.0f / (tot + 1e-8f);
#pragma unroll
    for (int i = 0; i < 8; i++) {
        float v = loc[i] * inv;
        row[tid + 256 * i] = v;
        rowb[tid + 256 * i] = __float2bfloat16(v);
    }
}

// ---------------- FUSED: BIG GEMM v4 (blocks 0..1023) + bdelta split-K (blocks 1024..1151) ----------------
#define B4_ABY (256 * 80)   // 20480 B per A stage
#define B4_BBY (32 * 144)   // 4608 B per B stage
#define B4_STG (B4_ABY + B4_BBY)
#define B4_SMEM (2 * B4_STG)   // 50176 B (dynamic)

__global__ void __launch_bounds__(256, 2) big_mma_kernel(
    const __nv_bfloat16* __restrict__ Ab, const __nv_bfloat16* __restrict__ Bb,
    const float* __restrict__ Wbase, float* __restrict__ C,
    const float* __restrict__ alpha, const float* __restrict__ pool,
    float* __restrict__ bt)
{
    extern __shared__ __align__(16) char dsm[];
    int tid = threadIdx.x, lane = tid & 31, wid = tid >> 5;

    if (blockIdx.x >= 1024) {
        // ---------------- bdelta branch ----------------
        int id = blockIdx.x - 1024;          // 0..127, orig grid (x=4, y=4, z=8)
        int bx = id & 3, by = (id >> 2) & 3, z = id >> 4;
        int m0 = by * 64, n0 = bx * 64;
        int kbeg = z * BDK;
        float* As = (float*)dsm;             // [16][64]
        float* Bs = As + 16 * 64;            // [16][64]
        int am = tid >> 2, ak = (tid & 3) * 4;
        int bk = tid >> 4, bn = (tid & 15) * 4;
        int ty = tid >> 4, tx = tid & 15;
        float acc[4][4] = {};
        const float* Ap = alpha + (size_t)(m0 + am) * NP + kbeg + ak;
        const float* Bp = pool + 4096 + (size_t)(kbeg + bk) * DP + n0 + bn;
        float4 av = *(const float4*)Ap;
        float4 bv = *(const float4*)Bp;
        for (int k0 = 0; k0 < BDK; k0 += 16) {
            As[(ak + 0) * 64 + am] = av.x; As[(ak + 1) * 64 + am] = av.y;
            As[(ak + 2) * 64 + am] = av.z; As[(ak + 3) * 64 + am] = av.w;
            *(float4*)&Bs[bk * 64 + bn] = bv;
            __syncthreads();
            if (k0 + 16 < BDK) {
                av = *(const float4*)(Ap + (k0 + 16));
                bv = *(const float4*)(Bp + (size_t)(k0 + 16) * DP);
            }
#pragma unroll
            for (int kk = 0; kk < 16; kk++) {
                float ar[4], br[4];
                *(float4*)ar = *(const float4*)&As[kk * 64 + ty * 4];
                *(float4*)br = *(const float4*)&Bs[kk * 64 + tx * 4];
#pragma unroll
                for (int i = 0; i < 4; i++)
#pragma unroll
                    for (int j = 0; j < 4; j++) acc[i][j] += ar[i] * br[j];
            }
            __syncthreads();
        }
        float* outp = bt + (size_t)z * BATCH * DB;
#pragma unroll
        for (int i = 0; i < 4; i++)
#pragma unroll
            for (int j = 0; j < 4; j++)
                outp[(size_t)(m0 + ty * 4 + i) * DB + n0 + tx * 4 + j] = acc[i][j];
        return;
    }

    // ---------------- big GEMM branch ----------------
    int warp_m = wid;                 // 0..7, rows warp_m*32 .. +31
    int n0 = blockIdx.x * 64;

    uint32_t sa = smem_u32(dsm);

    int ar = tid >> 2, aseg = tid & 3;     // A: rows ar+{0,64,128,192}, 4 segs
    int br = tid >> 3, bseg = tid & 7;     // B: 32 rows x 8 segs of 16B
    const __nv_bfloat16* Agb = Ab;
    const __nv_bfloat16* Bgb = Bb + n0;

    float acc[2][8][4];
#pragma unroll
    for (int i = 0; i < 2; i++)
#pragma unroll
        for (int j = 0; j < 8; j++)
#pragma unroll
            for (int q = 0; q < 4; q++) acc[i][j][q] = 0.0f;

    const int NC = NP / 32;   // 64
#define B_ISSUE(cc, ss) do { \
    uint32_t ab = sa + (ss) * B4_STG, bbf = ab + B4_ABY; \
    cpa16(ab + (uint32_t)ar * 80 + aseg * 16, Agb + (size_t)ar * NP + (cc) * 32 + aseg * 8); \
    cpa16(ab + (uint32_t)(ar + 64) * 80 + aseg * 16, Agb + (size_t)(ar + 64) * NP + (cc) * 32 + aseg * 8); \
    cpa16(ab + (uint32_t)(ar + 128) * 80 + aseg * 16, Agb + (size_t)(ar + 128) * NP + (cc) * 32 + aseg * 8); \
    cpa16(ab + (uint32_t)(ar + 192) * 80 + aseg * 16, Agb + (size_t)(ar + 192) * NP + (cc) * 32 + aseg * 8); \
    cpa16(bbf + (uint32_t)br * 144 + bseg * 16, Bgb + (size_t)((cc) * 32 + br) * NDE + bseg * 8); \
} while (0)

    B_ISSUE(0, 0); CP_COMMIT();
    B_ISSUE(1, 1); CP_COMMIT();
    CP_WAIT1(); __syncthreads();

    uint32_t a_lm = (uint32_t)(warp_m * 32 + (lane & 15)) * 80 + (lane >> 4) * 16;
    uint32_t b_k = (uint32_t)(lane & 15) * 144;
    uint32_t b_c = (uint32_t)(lane >> 4) * 16;

    for (int c = 0; c < NC; c++) {
        int buf = c & 1;
        uint32_t ab = sa + buf * B4_STG, bbf = ab + B4_ABY;
#pragma unroll
        for (int k16 = 0; k16 < 2; k16++) {
            uint32_t af[2][4];
            uint32_t bf[8][2];
#pragma unroll
            for (int mt = 0; mt < 2; mt++)
                ldmat_x4(af[mt][0], af[mt][1], af[mt][2], af[mt][3],
                         ab + a_lm + mt * 16 * 80 + k16 * 32);
#pragma unroll
            for (int bt2 = 0; bt2 < 4; bt2++) {
                uint32_t addr = bbf + b_k + (uint32_t)(k16 * 16) * 144 + b_c + bt2 * 32;
                uint32_t r0, r1, r2, r3;
                ldmat_x4_t(r0, r1, r2, r3, addr);
                bf[2 * bt2 + 0][0] = r0; bf[2 * bt2 + 0][1] = r1;
                bf[2 * bt2 + 1][0] = r2; bf[2 * bt2 + 1][1] = r3;
            }
#pragma unroll
            for (int mt = 0; mt < 2; mt++)
#pragma unroll
                for (int nt = 0; nt < 8; nt++)
                    mma_bf16(acc[mt][nt], af[mt], bf[nt]);
        }
        __syncthreads();
        if (c + 2 < NC) B_ISSUE(c + 2, buf);
        CP_COMMIT();
        CP_WAIT1();
        __syncthreads();
    }
#undef B_ISSUE

#pragma unroll
    for (int mt = 0; mt < 2; mt++) {
        int row = warp_m * 32 + mt * 16 + (lane >> 2);
        float* c0 = C + (size_t)row * NDE + n0;
        float* c1 = C + (size_t)(row + 8) * NDE + n0;
        const float* wb = Wbase + n0;
#pragma unroll
        for (int nt = 0; nt < 8; nt++) {
            int col = nt * 8 + (lane & 3) * 2;
            float2 w2 = *(const float2*)(wb + col);
            float2 o0, o1;
            o0.x = acc[mt][nt][0] + w2.x; o0.y = acc[mt][nt][1] + w2.y;
            o1.x = acc[mt][nt][2] + w2.x; o1.y = acc[mt][nt][3] + w2.y;
            *(float2*)(c0 + col) = o0;
            *(float2*)(c1 + col) = o1;
        }
    }
}

// ---------------- h_t + residual + LayerNorm (sums b_delta partials) ----------------
__global__ void ht_ln_kernel(const float* __restrict__ Wout, const float* __restrict__ hA,
                             const float* __restrict__ bparts, const float* __restrict__ b_base,
                             const float* __restrict__ gamma_p, const float* __restrict__ ln_s,
                             const float* __restrict__ ln_b, float* __restrict__ hmid)
{
    int b = blockIdx.x, tid = threadIdx.x;     // 256 threads
    int lane = tid & 31, warp = tid >> 5;
    __shared__ float hs[DA];
    __shared__ float ys[DA];
    __shared__ float bsum[DB];
    hs[tid] = hA[(size_t)b * DA + tid];
    {
        float bs = 0.0f;
#pragma unroll
        for (int ks = 0; ks < BDS; ks++)
            bs += bparts[(size_t)ks * BATCH * DB + (size_t)b * DB + tid];
        bsum[tid] = bs;
    }
    __syncthreads();
    float gamma = gamma_p[0];
    const float* Wb = Wout + (size_t)b * NDE;
    for (int c = warp; c < DB; c += 8) {
        const float* row = Wb + (size_t)c * DA;
        float s = 0.0f;
#pragma unroll
        for (int i = 0; i < 8; i++) { int a = lane + 32 * i; s += row[a] * hs[a]; }
#pragma unroll
        for (int o = 16; o; o >>= 1) s += __shfl_xor_sync(0xffffffffu, s, o);
        if (lane == 0) {
            float htv = s + bsum[c] + b_base[c];
            ys[c] = hs[c] + gamma * htv;
        }
    }
    __syncthreads();
    float v = ys[tid];
    float s1 = v, s2 = v * v;
#pragma unroll
    for (int o = 16; o; o >>= 1) {
        s1 += __shfl_xor_sync(0xffffffffu, s1, o);
        s2 += __shfl_xor_sync(0xffffffffu, s2, o);
    }
    __shared__ float red[18];
    if (lane == 0) { red[warp] = s1; red[8 + warp] = s2; }
    __syncthreads();
    if (tid == 0) {
        float a = 0.0f, q = 0.0f;
#pragma unroll
        for (int i = 0; i < 8; i++) { a += red[i]; q += red[8 + i]; }
        red[16] = a / (float)DA;
        red[17] = q / (float)DA;
    }
    __syncthreads();
    float mu = red[16];
    float var = fmaxf(red[17] - mu * mu, 0.0f);
    float r = rsqrtf(var + 1e-6f);
    hmid[(size_t)b * DA + tid] = (v - mu) * r * ln_s[tid] + ln_b[tid];
}

// ---------------- launch ----------------
extern "C" void kernel_launch(void* const* d_in, const int* in_sizes, int n_in,
                              void* d_out, int out_size)
{
    const float* x      = (const float*)d_in[0];
    const float* pool   = (const float*)d_in[1];
    const float* A_w0   = (const float*)d_in[2];
    const float* A_b0   = (const float*)d_in[3];
    const float* A_w1   = (const float*)d_in[4];
    const float* A_b1   = (const float*)d_in[5];
    const float* W_Q    = (const float*)d_in[6];
    const float* W_K    = (const float*)d_in[7];
    const float* logits = (const float*)d_in[8];
    const float* tau    = (const float*)d_in[9];
    const float* W_base = (const float*)d_in[10];
    const float* b_base = (const float*)d_in[11];
    const float* gamma  = (const float*)d_in[12];
    const float* ln_s   = (const float*)d_in[13];
    const float* ln_b   = (const float*)d_in[14];
    const float* B_w0   = (const float*)d_in[15];
    const float* B_b0   = (const float*)d_in[16];
    const float* B_w1   = (const float*)d_in[17];
    const float* B_b1   = (const float*)d_in[18];

    float* out       = (float*)d_out;
    float* out_alpha = out + OUT_ALPHA;
    float* out_W     = out + OUT_W;
    float* out_keys  = out + OUT_KEYS;

    float *p_hid, *p_hA, *p_qw, *p_kn, *p_bt, *p_hmid, *p_hid2, *p_kp;
    __nv_bfloat16 *p_ab, *p_UVb, *p_px, *p_wx;
    cudaGetSymbolAddress((void**)&p_hid,  g_hid);
    cudaGetSymbolAddress((void**)&p_hA,   g_hA);
    cudaGetSymbolAddress((void**)&p_qw,   g_qw);
    cudaGetSymbolAddress((void**)&p_kn,   g_kn);
    cudaGetSymbolAddress((void**)&p_bt,   g_bt);
    cudaGetSymbolAddress((void**)&p_hmid, g_hmid);
    cudaGetSymbolAddress((void**)&p_hid2, g_hid2);
    cudaGetSymbolAddress((void**)&p_kp,   g_kp);
    cudaGetSymbolAddress((void**)&p_ab,   g_alphab);
    cudaGetSymbolAddress((void**)&p_UVb,  g_UVb);
    cudaGetSymbolAddress((void**)&p_px,   g_poolx);
    cudaGetSymbolAddress((void**)&p_wx,   g_wkx);

    cudaFuncSetAttribute(big_mma_kernel, cudaFuncAttributeMaxDynamicSharedMemorySize, B4_SMEM);

    // 1-2) hi/lo expansions
    expand_pool_kernel<<<NP, 256>>>(pool, p_px);
    expand_wk_kernel<<<KEXP, 256>>>(W_K, p_wx);
    // 3) first MLP gemm (independent -> fused keys+uv is launch #4, profiled)
    gemm64<1><<<dim3(HIDN / 64, BATCH / 64), 256>>>(x, A_w0, A_b0, p_hid, DMODEL, DMODEL, HIDN, HIDN);
    // 4) FUSED keys split-bf16 mma (1024 blocks) + UV build f32x2 (2048 blocks)
    keys_uv_kernel<<<3072, 128>>>(p_px, p_wx, p_kp, pool, p_UVb);
    // 5) reduce + keys output + k_norm
    knorm_kernel<<<dim3(NP, SA), 64>>>(p_kp, out_keys, p_kn);
    // 6-7) h_A MLP second gemm + queries
    gemm64<0><<<dim3(DA / 64, BATCH / 64), 256>>>(p_hid, A_w1, A_b1, p_hA, HIDN, HIDN, DA, DA);
    q_kernel<<<dim3(BATCH, SA), 64>>>(p_hA, W_Q, logits, p_qw);
    // 8-9) scores -> alpha
    scores_kernel<<<dim3(NP / 64, BATCH / 64), 256>>>(p_qw, p_kn, tau, out_alpha);
    alpha_norm_kernel<<<BATCH, 256>>>(out_alpha, p_ab);
    // 10) FUSED big GEMM (1024 blocks) + bdelta split-K (128 blocks)
    big_mma_kernel<<<1152, 256, B4_SMEM>>>(p_ab, p_UVb, W_base, out_W, out_alpha, pool, p_bt);
    // 11) h_t, residual, layernorm (sums bdelta partials)
    ht_ln_kernel<<<BATCH, 256>>>(out_W, p_hA, p_bt, b_base, gamma, ln_s, ln_b, p_hmid);
    // 12-13) output MLP
    gemm64<1><<<dim3(HIDN / 64, BATCH / 64), 256>>>(p_hmid, B_w0, B_b0, p_hid2, DA, DA, HIDN, HIDN);
    gemm64<0><<<dim3(DMODEL / 64, BATCH / 64), 256>>>(p_hid2, B_w1, B_b1, out, HIDN, HIDN, DMODEL, DMODEL);
}

// round 17
// speedup vs baseline: 1.0721x; 1.0098x over previous
#include <cuda_runtime.h>
#include <cuda_bf16.h>
#include <cstdint>
#include <cstddef>

// ---------------- problem constants ----------------
#define BATCH  256
#define DMODEL 512
#define DA     256
#define DB     256
#define RR     8
#define NP     2048
#define DP     4608
#define SA     4
#define DKK    64
#define HIDN   1024
#define NDE    65536           // DB*DA
#define KEXP   13824           // 3*DP (hi | lo | hi)
#define KZ     8               // keys split-K
#define KZLEN  (KEXP / KZ)     // 1728
#define BDS    8               // b_delta split-K
#define BDK    (NP / BDS)      // 256

// output layout (flattened tuple: output, alpha, W_assembled, keys)
#define OUT_ALPHA  (BATCH*DMODEL)
#define OUT_W      (OUT_ALPHA + BATCH*NP)
#define OUT_KEYS   (OUT_W + (size_t)BATCH*DB*DA)

// ---------------- scratch (device globals; no allocation allowed) ----------------
__device__ float g_hid [BATCH*HIDN];
__device__ float g_hA  [BATCH*DA];
__device__ float g_qw  [BATCH*SA*DKK];
__device__ float g_kn  [NP*SA*DKK];
__device__ float g_bt  [BDS*BATCH*DB];                  // b_delta split-K partials (2MB)
__device__ float g_hmid[BATCH*DA];
__device__ float g_hid2[BATCH*HIDN];
__device__ float g_kp  [KZ*NP*SA*DKK];                  // keys split-K partials (16MB)
__device__ __nv_bfloat16 g_alphab[BATCH*NP];            // alpha in bf16
__device__ __nv_bfloat16 g_UVb[(size_t)NP*NDE];         // UV in bf16 (268MB)
__device__ __nv_bfloat16 g_poolx[(size_t)NP*KEXP];      // pool hi/lo expanded (56.6MB)
__device__ __nv_bfloat16 g_wkx[(size_t)KEXP*256];       // W_K hi/lo expanded (7MB)

// ---------------- helpers ----------------
__device__ __forceinline__ float gelu_f(float x) {
    const float c = 0.7978845608028654f;
    return 0.5f * x * (1.0f + tanhf(c * (x + 0.044715f * x * x * x)));
}
__device__ __forceinline__ uint32_t smem_u32(const void* p) {
    uint32_t a;
    asm("{ .reg .u64 t; cvta.to.shared.u64 t, %1; cvt.u32.u64 %0, t; }" : "=r"(a) : "l"(p));
    return a;
}
__device__ __forceinline__ void ldmat_x4(uint32_t& r0, uint32_t& r1, uint32_t& r2, uint32_t& r3,
                                         uint32_t addr) {
    asm volatile("ldmatrix.sync.aligned.m8n8.x4.shared.b16 {%0,%1,%2,%3}, [%4];"
                 : "=r"(r0), "=r"(r1), "=r"(r2), "=r"(r3) : "r"(addr));
}
__device__ __forceinline__ void ldmat_x4_t(uint32_t& r0, uint32_t& r1, uint32_t& r2, uint32_t& r3,
                                           uint32_t addr) {
    asm volatile("ldmatrix.sync.aligned.m8n8.x4.trans.shared.b16 {%0,%1,%2,%3}, [%4];"
                 : "=r"(r0), "=r"(r1), "=r"(r2), "=r"(r3) : "r"(addr));
}
__device__ __forceinline__ void mma_bf16(float* d, const uint32_t* a, const uint32_t* b) {
    asm volatile("mma.sync.aligned.m16n8k16.row.col.f32.bf16.bf16.f32 "
                 "{%0,%1,%2,%3}, {%4,%5,%6,%7}, {%8,%9}, {%0,%1,%2,%3};"
                 : "+f"(d[0]), "+f"(d[1]), "+f"(d[2]), "+f"(d[3])
                 : "r"(a[0]), "r"(a[1]), "r"(a[2]), "r"(a[3]), "r"(b[0]), "r"(b[1]));
}
__device__ __forceinline__ void cpa16(uint32_t dst, const void* src) {
    asm volatile("cp.async.cg.shared.global [%0], [%1], 16;" :: "r"(dst), "l"(src));
}
#define CP_COMMIT() asm volatile("cp.async.commit_group;" ::: "memory")
#define CP_WAIT1()  asm volatile("cp.async.wait_group 1;" ::: "memory")
#define CP_WAIT2()  asm volatile("cp.async.wait_group 2;" ::: "memory")

// packed f32x2 fma
__device__ __forceinline__ unsigned long long dupf2(float a) {
    unsigned long long r; unsigned int u = __float_as_uint(a);
    asm("mov.b64 %0, {%1, %1};" : "=l"(r) : "r"(u));
    return r;
}
__device__ __forceinline__ unsigned long long packf2(float lo, float hi) {
    unsigned long long r;
    asm("mov.b64 %0, {%1, %2};" : "=l"(r) : "r"(__float_as_uint(lo)), "r"(__float_as_uint(hi)));
    return r;
}
__device__ __forceinline__ void fma2(unsigned long long& d, unsigned long long a, unsigned long long b) {
    asm("fma.rn.f32x2 %0, %1, %2, %0;" : "+l"(d) : "l"(a), "l"(b));
}
__device__ __forceinline__ float2 unpkf2(unsigned long long v) {
    unsigned int lo, hi;
    asm("mov.b64 {%0, %1}, %2;" : "=r"(lo), "=r"(hi) : "l"(v));
    return make_float2(__uint_as_float(lo), __uint_as_float(hi));
}

// ---------------- generic 64x64x16 SGEMM body (shared by gemm64 + prologue) ----------------
template <int ACT>
__device__ __forceinline__ void gemm64_body(
    const float* __restrict__ A, const float* __restrict__ B,
    const float* __restrict__ bias, float* __restrict__ C,
    int K, int lda, int ldb, int ldc, int m0, int n0,
    float (*As)[64], float (*Bs)[64])
{
    int tid = threadIdx.x;
    int am = tid >> 2, ak = (tid & 3) * 4;
    int bk = tid >> 4, bn = (tid & 15) * 4;
    int ty = tid >> 4, tx = tid & 15;
    float acc[4][4] = {};
    const float* Ap = A + (size_t)(m0 + am) * lda + ak;
    const float* Bp = B + (size_t)bk * ldb + n0 + bn;
    float4 av = *(const float4*)Ap;
    float4 bv = *(const float4*)Bp;
    for (int k0 = 0; k0 < K; k0 += 16) {
        As[ak + 0][am] = av.x; As[ak + 1][am] = av.y; As[ak + 2][am] = av.z; As[ak + 3][am] = av.w;
        *(float4*)&Bs[bk][bn] = bv;
        __syncthreads();
        if (k0 + 16 < K) {
            av = *(const float4*)(Ap + (k0 + 16));
            bv = *(const float4*)(Bp + (size_t)(k0 + 16) * ldb);
        }
#pragma unroll
        for (int kk = 0; kk < 16; kk++) {
            float ar[4], br[4];
            *(float4*)ar = *(const float4*)&As[kk][ty * 4];
            *(float4*)br = *(const float4*)&Bs[kk][tx * 4];
#pragma unroll
            for (int i = 0; i < 4; i++)
#pragma unroll
                for (int j = 0; j < 4; j++) acc[i][j] += ar[i] * br[j];
        }
        __syncthreads();
    }
#pragma unroll
    for (int i = 0; i < 4; i++) {
        int m = m0 + ty * 4 + i;
#pragma unroll
        for (int j = 0; j < 4; j++) {
            int n = n0 + tx * 4 + j;
            float c = acc[i][j];
            if (bias) c += bias[n];
            if (ACT == 1) c = gelu_f(c);
            C[(size_t)m * ldc + n] = c;
        }
    }
}

template <int ACT>
__global__ void gemm64(const float* __restrict__ A, const float* __restrict__ B,
                       const float* __restrict__ bias, float* __restrict__ C,
                       int K, int lda, int ldb, int ldc)
{
    __shared__ float As[16][64];
    __shared__ float Bs[16][64];
    gemm64_body<ACT>(A, B, bias, C, K, lda, ldb, ldc, blockIdx.y * 64, blockIdx.x * 64, As, Bs);
}

// ---------------- FUSED PROLOGUE: expand_pool (0..2047) + expand_wk (2048..2911) + gemm#1 (2912..2975) ----------------
__global__ void prologue_kernel(const float* __restrict__ pool, __nv_bfloat16* __restrict__ px,
                                const float* __restrict__ WK, __nv_bfloat16* __restrict__ wx,
                                const float* __restrict__ x, const float* __restrict__ A_w0,
                                const float* __restrict__ A_b0, float* __restrict__ hid)
{
    __shared__ float As[16][64];
    __shared__ float Bs[16][64];
    int bid = blockIdx.x, tid = threadIdx.x;

    if (bid < 2048) {
        // expand_pool: n = bid
        const float* src = pool + (size_t)bid * DP;
        __nv_bfloat16* dst = px + (size_t)bid * KEXP;
#pragma unroll 2
        for (int p = tid; p < DP; p += 256) {
            float v = src[p];
            __nv_bfloat16 hi = __float2bfloat16(v);
            __nv_bfloat16 lo = __float2bfloat16(v - __bfloat162float(hi));
            dst[p] = hi;
            dst[DP + p] = lo;
            dst[2 * DP + p] = hi;
        }
        return;
    }
    if (bid < 2912) {
        // expand_wk: 16 k-rows per block
        int kb = (bid - 2048) * 16;
        int a = tid >> 6, q = tid & 63;
#pragma unroll 4
        for (int kk = 0; kk < 16; kk++) {
            int k = kb + kk;
            int s = k / DP, p = k % DP;
            float v = WK[(size_t)a * DP * DKK + (size_t)p * DKK + q];
            __nv_bfloat16 hi = __float2bfloat16(v);
            __nv_bfloat16 o = (s < 2) ? hi : __float2bfloat16(v - __bfloat162float(hi));
            wx[(size_t)k * 256 + tid] = o;
        }
        return;
    }
    // gemm64<1>: hid = gelu(x @ A_w0 + A_b0); orig grid (x=16 n-tiles, y=4 m-tiles)
    int id = bid - 2912;
    gemm64_body<1>(x, A_w0, A_b0, hid, DMODEL, DMODEL, HIDN, HIDN,
                   (id >> 4) * 64, (id & 15) * 64, As, Bs);
}

// ---------------- FUSED: keys mma (blocks 0..1023) + UV build (blocks 1024..3071) ----------------
#define K_ABY (64 * 80)     // 5120 B
#define K_BBY (32 * 144)    // 4608 B
#define K_STG (K_ABY + K_BBY)

__global__ void __launch_bounds__(128, 4) keys_uv_kernel(
    const __nv_bfloat16* __restrict__ Ax, const __nv_bfloat16* __restrict__ Bx,
    float* __restrict__ kp, const float* __restrict__ pool, __nv_bfloat16* __restrict__ UV)
{
    __shared__ __align__(16) char smem[4 * K_STG];   // 38912 B
    int tid = threadIdx.x;
    int bid = blockIdx.x;

    if (bid >= 1024) {
        // ---------------- UV branch: adjacent cols 2*tid, 2*tid+1, packed store ----------------
        int n = bid - 1024;
        float* Us = (float*)smem;                     // 2048 floats
        const float* p = pool + (size_t)n * DP;
        for (int i = tid; i < DB * RR; i += 128) Us[i] = p[i];
        unsigned long long vv[RR];
#pragma unroll
        for (int r = 0; r < RR; r++) {
            float2 v2 = *(const float2*)(p + 2048 + r * 256 + 2 * tid);
            vv[r] = packf2(v2.x, v2.y);
        }
        __syncthreads();
        __nv_bfloat16* out = UV + (size_t)n * NDE + 2 * tid;
#pragma unroll 2
        for (int d = 0; d < DB; d++) {
            unsigned long long acc2 = 0ULL;
#pragma unroll
            for (int r = 0; r < RR; r++)
                fma2(acc2, dupf2(Us[d * RR + r]), vv[r]);
            float2 a = unpkf2(acc2);
            __nv_bfloat162 h;
            h.x = __float2bfloat16(a.x);
            h.y = __float2bfloat16(a.y);
            *(__nv_bfloat162*)(out + (size_t)d * 256) = h;
        }
        return;
    }

    // ---------------- keys branch ----------------
    int lane = tid & 31, wid = tid >> 5;
    int warp_m = wid & 1, warp_n = wid >> 1;
    int bx = bid & 3, by = (bid >> 2) & 31, z = bid >> 7;
    int n0 = bx * 64;
    int m0 = by * 64;
    int kbase = z * KZLEN;

    uint32_t sbase = smem_u32(smem);
    int ar = tid >> 2, aseg = tid & 3;
    int br = tid >> 3, bseg = tid & 7;
    const __nv_bfloat16* Agb = Ax + (size_t)m0 * KEXP + kbase;
    const __nv_bfloat16* Bgb = Bx + (size_t)kbase * 256 + n0;

    float acc[2][4][4];
#pragma unroll
    for (int i = 0; i < 2; i++)
#pragma unroll
        for (int j = 0; j < 4; j++)
#pragma unroll
            for (int q = 0; q < 4; q++) acc[i][j][q] = 0.0f;

    const int NC = KZLEN / 32;   // 54
#define K_ISSUE(cc, ss) do { \
    uint32_t ab = sbase + (ss) * K_STG, bbf = ab + K_ABY; \
    cpa16(ab + (uint32_t)ar * 80 + aseg * 16, Agb + (size_t)ar * KEXP + (cc) * 32 + aseg * 8); \
    cpa16(ab + (uint32_t)(ar + 32) * 80 + aseg * 16, Agb + (size_t)(ar + 32) * KEXP + (cc) * 32 + aseg * 8); \
    cpa16(bbf + (uint32_t)br * 144 + bseg * 16, Bgb + (size_t)((cc) * 32 + br) * 256 + bseg * 8); \
    cpa16(bbf + (uint32_t)(br + 16) * 144 + bseg * 16, Bgb + (size_t)((cc) * 32 + br + 16) * 256 + bseg * 8); \
} while (0)

    K_ISSUE(0, 0); CP_COMMIT();
    K_ISSUE(1, 1); CP_COMMIT();
    K_ISSUE(2, 2); CP_COMMIT();

    uint32_t a_lm = (uint32_t)(warp_m * 32 + (lane & 15)) * 80 + (lane >> 4) * 16;
    uint32_t b_k = (uint32_t)(lane & 15) * 144;
    uint32_t b_c = (uint32_t)(warp_n * 32 + (lane >> 4) * 8) * 2;

    for (int c = 0; c < NC; c++) {
        CP_WAIT2();
        __syncthreads();
        if (c + 3 < NC) K_ISSUE(c + 3, (c + 3) & 3);
        CP_COMMIT();
        uint32_t ab = sbase + (c & 3) * K_STG, bbf = ab + K_ABY;
#pragma unroll
        for (int k16 = 0; k16 < 2; k16++) {
            uint32_t af[2][4];
            uint32_t bf[4][2];
#pragma unroll
            for (int mt = 0; mt < 2; mt++)
                ldmat_x4(af[mt][0], af[mt][1], af[mt][2], af[mt][3],
                         ab + a_lm + mt * 16 * 80 + k16 * 32);
#pragma unroll
            for (int bt = 0; bt < 2; bt++) {
                uint32_t addr = bbf + b_k + (uint32_t)(k16 * 16) * 144 + b_c + bt * 32;
                uint32_t r0, r1, r2, r3;
                ldmat_x4_t(r0, r1, r2, r3, addr);
                bf[2 * bt + 0][0] = r0; bf[2 * bt + 0][1] = r1;
                bf[2 * bt + 1][0] = r2; bf[2 * bt + 1][1] = r3;
            }
#pragma unroll
            for (int mt = 0; mt < 2; mt++)
#pragma unroll
                for (int nt = 0; nt < 4; nt++)
                    mma_bf16(acc[mt][nt], af[mt], bf[nt]);
        }
    }
#undef K_ISSUE

    float* outp = kp + (size_t)z * NP * (SA * DKK);
#pragma unroll
    for (int mt = 0; mt < 2; mt++) {
        int row = m0 + warp_m * 32 + mt * 16 + (lane >> 2);
        float* c0 = outp + (size_t)row * 256;
        float* c1 = outp + (size_t)(row + 8) * 256;
#pragma unroll
        for (int nt = 0; nt < 4; nt++) {
            int col = n0 + warp_n * 32 + nt * 8 + (lane & 3) * 2;
            *(float2*)(c0 + col) = make_float2(acc[mt][nt][0], acc[mt][nt][1]);
            *(float2*)(c1 + col) = make_float2(acc[mt][nt][2], acc[mt][nt][3]);
        }
    }
}

// ---------------- reduce partials -> keys output + normalized keys ----------------
__global__ void knorm_kernel(const float* __restrict__ kp, float* __restrict__ keys,
                             float* __restrict__ kn)
{
    int n = blockIdx.x, a = blockIdx.y, tid = threadIdx.x;  // 64 threads
    size_t idx = (size_t)n * (SA * DKK) + a * DKK + tid;
    float v = 0.0f;
#pragma unroll
    for (int ks = 0; ks < KZ; ks++) v += kp[(size_t)ks * NP * (SA * DKK) + idx];
    keys[idx] = v;
    float ss = v * v;
#pragma unroll
    for (int o = 16; o; o >>= 1) ss += __shfl_xor_sync(0xffffffffu, ss, o);
    __shared__ float r2[2];
    if ((tid & 31) == 0) r2[tid >> 5] = ss;
    __syncthreads();
    float nrm = sqrtf(r2[0] + r2[1]);
    kn[idx] = v / (nrm + 1e-8f);
}

// ---------------- queries ----------------
__global__ void q_kernel(const float* __restrict__ hA, const float* __restrict__ WQ,
                         const float* __restrict__ logits, float* __restrict__ qw)
{
    int b = blockIdx.x, a = blockIdx.y, tid = threadIdx.x;  // 64 threads
    __shared__ float hs[DA];
    for (int i = tid; i < DA; i += 64) hs[i] = hA[(size_t)b * DA + i];
    __syncthreads();
    float q = 0.0f;
    const float* w = WQ + (size_t)a * DA * DKK + tid;
#pragma unroll 4
    for (int d = 0; d < DA; d++) q += hs[d] * w[(size_t)d * DKK];
    float ss = q * q;
#pragma unroll
    for (int o = 16; o; o >>= 1) ss += __shfl_xor_sync(0xffffffffu, ss, o);
    __shared__ float r2[2];
    if ((tid & 31) == 0) r2[tid >> 5] = ss;
    __syncthreads();
    float nrm = sqrtf(r2[0] + r2[1]);
    float l0 = logits[0], l1 = logits[1], l2 = logits[2], l3 = logits[3];
    float m = fmaxf(fmaxf(l0, l1), fmaxf(l2, l3));
    float e0 = expf(l0 - m), e1 = expf(l1 - m), e2 = expf(l2 - m), e3 = expf(l3 - m);
    float ea = (a == 0) ? e0 : (a == 1) ? e1 : (a == 2) ? e2 : e3;
    float wa = ea / (e0 + e1 + e2 + e3);
    qw[(size_t)b * (SA * DKK) + a * DKK + tid] = wa * q / (nrm + 1e-8f);
}

// ---------------- scores + gate/exp -> alpha_raw ----------------
__global__ void scores_kernel(const float* __restrict__ QW, const float* __restrict__ KN,
                              const float* __restrict__ tau_p, float* __restrict__ alpha)
{
    int n0 = blockIdx.x * 64, m0 = blockIdx.y * 64;
    __shared__ float As[16][64];
    __shared__ float Bs[16][64];
    int tid = threadIdx.x;
    int am = tid >> 2, ak = (tid & 3) * 4;
    int bn = tid >> 2, bk = (tid & 3) * 4;
    int ty = tid >> 4, tx = tid & 15;
    float acc[4][4] = {};
    for (int k0 = 0; k0 < 256; k0 += 16) {
        float4 av = *(const float4*)(QW + (size_t)(m0 + am) * 256 + k0 + ak);
        As[ak + 0][am] = av.x; As[ak + 1][am] = av.y; As[ak + 2][am] = av.z; As[ak + 3][am] = av.w;
        float4 bv = *(const float4*)(KN + (size_t)(n0 + bn) * 256 + k0 + bk);
        Bs[bk + 0][bn] = bv.x; Bs[bk + 1][bn] = bv.y; Bs[bk + 2][bn] = bv.z; Bs[bk + 3][bn] = bv.w;
        __syncthreads();
#pragma unroll
        for (int kk = 0; kk < 16; kk++) {
            float ar[4], br[4];
            *(float4*)ar = *(const float4*)&As[kk][ty * 4];
            *(float4*)br = *(const float4*)&Bs[kk][tx * 4];
#pragma unroll
            for (int i = 0; i < 4; i++)
#pragma unroll
                for (int j = 0; j < 4; j++) acc[i][j] += ar[i] * br[j];
        }
        __syncthreads();
    }
    float tau = tau_p[0];
#pragma unroll
    for (int i = 0; i < 4; i++)
#pragma unroll
        for (int j = 0; j < 4; j++) {
            float s = acc[i][j];
            float g = 1.0f / (1.0f + expf(-(s - tau)));
            alpha[(size_t)(m0 + ty * 4 + i) * NP + n0 + tx * 4 + j] = g * expf(s);
        }
}

// ---------------- alpha row normalization (+ bf16 copy) ----------------
__global__ void alpha_norm_kernel(float* __restrict__ alpha, __nv_bfloat16* __restrict__ ab)
{
    int b = blockIdx.x, tid = threadIdx.x;  // 256 threads
    float* row = alpha + (size_t)b * NP;
    __nv_bfloat16* rowb = ab + (size_t)b * NP;
    float loc[8]; float s = 0.0f;
#pragma unroll
    for (int i = 0; i < 8; i++) { loc[i] = row[tid + 256 * i]; s += loc[i]; }
#pragma unroll
    for (int o = 16; o; o >>= 1) s += __shfl_xor_sync(0xffffffffu, s, o);
    __shared__ float red[8];
    if ((tid & 31) == 0) red[tid >> 5] = s;
    __syncthreads();
    float tot = 0.0f;
#pragma unroll
    for (int i = 0; i < 8; i++) tot += red[i];
    float inv = 1.0f / (tot + 1e-8f);
#pragma unroll
    for (int i = 0; i < 8; i++) {
        float v = loc[i] * inv;
        row[tid + 256 * i] = v;
        rowb[tid + 256 * i] = __float2bfloat16(v);
    }
}

// ---------------- FUSED: BIG GEMM v4 (blocks 0..1023) + bdelta split-K (blocks 1024..1151) ----------------
#define B4_ABY (256 * 80)   // 20480 B per A stage
#define B4_BBY (32 * 144)   // 4608 B per B stage
#define B4_STG (B4_ABY + B4_BBY)
#define B4_SMEM (2 * B4_STG)   // 50176 B (dynamic)

__global__ void __launch_bounds__(256, 2) big_mma_kernel(
    const __nv_bfloat16* __restrict__ Ab, const __nv_bfloat16* __restrict__ Bb,
    const float* __restrict__ Wbase, float* __restrict__ C,
    const float* __restrict__ alpha, const float* __restrict__ pool,
    float* __restrict__ bt)
{
    extern __shared__ __align__(16) char dsm[];
    int tid = threadIdx.x, lane = tid & 31, wid = tid >> 5;

    if (blockIdx.x >= 1024) {
        // ---------------- bdelta branch ----------------
        int id = blockIdx.x - 1024;          // 0..127, orig grid (x=4, y=4, z=8)
        int bx = id & 3, by = (id >> 2) & 3, z = id >> 4;
        int m0 = by * 64, n0 = bx * 64;
        int kbeg = z * BDK;
        float* As = (float*)dsm;             // [16][64]
        float* Bs = As + 16 * 64;            // [16][64]
        int am = tid >> 2, ak = (tid & 3) * 4;
        int bk = tid >> 4, bn = (tid & 15) * 4;
        int ty = tid >> 4, tx = tid & 15;
        float acc[4][4] = {};
        const float* Ap = alpha + (size_t)(m0 + am) * NP + kbeg + ak;
        const float* Bp = pool + 4096 + (size_t)(kbeg + bk) * DP + n0 + bn;
        float4 av = *(const float4*)Ap;
        float4 bv = *(const float4*)Bp;
        for (int k0 = 0; k0 < BDK; k0 += 16) {
            As[(ak + 0) * 64 + am] = av.x; As[(ak + 1) * 64 + am] = av.y;
            As[(ak + 2) * 64 + am] = av.z; As[(ak + 3) * 64 + am] = av.w;
            *(float4*)&Bs[bk * 64 + bn] = bv;
            __syncthreads();
            if (k0 + 16 < BDK) {
                av = *(const float4*)(Ap + (k0 + 16));
                bv = *(const float4*)(Bp + (size_t)(k0 + 16) * DP);
            }
#pragma unroll
            for (int kk = 0; kk < 16; kk++) {
                float ar[4], br[4];
                *(float4*)ar = *(const float4*)&As[kk * 64 + ty * 4];
                *(float4*)br = *(const float4*)&Bs[kk * 64 + tx * 4];
#pragma unroll
                for (int i = 0; i < 4; i++)
#pragma unroll
                    for (int j = 0; j < 4; j++) acc[i][j] += ar[i] * br[j];
            }
            __syncthreads();
        }
        float* outp = bt + (size_t)z * BATCH * DB;
#pragma unroll
        for (int i = 0; i < 4; i++)
#pragma unroll
            for (int j = 0; j < 4; j++)
                outp[(size_t)(m0 + ty * 4 + i) * DB + n0 + tx * 4 + j] = acc[i][j];
        return;
    }

    // ---------------- big GEMM branch ----------------
    int warp_m = wid;                 // 0..7, rows warp_m*32 .. +31
    int n0 = blockIdx.x * 64;

    uint32_t sa = smem_u32(dsm);

    int ar = tid >> 2, aseg = tid & 3;     // A: rows ar+{0,64,128,192}, 4 segs
    int br = tid >> 3, bseg = tid & 7;     // B: 32 rows x 8 segs of 16B
    const __nv_bfloat16* Agb = Ab;
    const __nv_bfloat16* Bgb = Bb + n0;

    float acc[2][8][4];
#pragma unroll
    for (int i = 0; i < 2; i++)
#pragma unroll
        for (int j = 0; j < 8; j++)
#pragma unroll
            for (int q = 0; q < 4; q++) acc[i][j][q] = 0.0f;

    const int NC = NP / 32;   // 64
#define B_ISSUE(cc, ss) do { \
    uint32_t ab = sa + (ss) * B4_STG, bbf = ab + B4_ABY; \
    cpa16(ab + (uint32_t)ar * 80 + aseg * 16, Agb + (size_t)ar * NP + (cc) * 32 + aseg * 8); \
    cpa16(ab + (uint32_t)(ar + 64) * 80 + aseg * 16, Agb + (size_t)(ar + 64) * NP + (cc) * 32 + aseg * 8); \
    cpa16(ab + (uint32_t)(ar + 128) * 80 + aseg * 16, Agb + (size_t)(ar + 128) * NP + (cc) * 32 + aseg * 8); \
    cpa16(ab + (uint32_t)(ar + 192) * 80 + aseg * 16, Agb + (size_t)(ar + 192) * NP + (cc) * 32 + aseg * 8); \
    cpa16(bbf + (uint32_t)br * 144 + bseg * 16, Bgb + (size_t)((cc) * 32 + br) * NDE + bseg * 8); \
} while (0)

    B_ISSUE(0, 0); CP_COMMIT();
    B_ISSUE(1, 1); CP_COMMIT();
    CP_WAIT1(); __syncthreads();

    uint32_t a_lm = (uint32_t)(warp_m * 32 + (lane & 15)) * 80 + (lane >> 4) * 16;
    uint32_t b_k = (uint32_t)(lane & 15) * 144;
    uint32_t b_c = (uint32_t)(lane >> 4) * 16;

    for (int c = 0; c < NC; c++) {
        int buf = c & 1;
        uint32_t ab = sa + buf * B4_STG, bbf = ab + B4_ABY;
#pragma unroll
        for (int k16 = 0; k16 < 2; k16++) {
            uint32_t af[2][4];
            uint32_t bf[8][2];
#pragma unroll
            for (int mt = 0; mt < 2; mt++)
                ldmat_x4(af[mt][0], af[mt][1], af[mt][2], af[mt][3],
                         ab + a_lm + mt * 16 * 80 + k16 * 32);
#pragma unroll
            for (int bt2 = 0; bt2 < 4; bt2++) {
                uint32_t addr = bbf + b_k + (uint32_t)(k16 * 16) * 144 + b_c + bt2 * 32;
                uint32_t r0, r1, r2, r3;
                ldmat_x4_t(r0, r1, r2, r3, addr);
                bf[2 * bt2 + 0][0] = r0; bf[2 * bt2 + 0][1] = r1;
                bf[2 * bt2 + 1][0] = r2; bf[2 * bt2 + 1][1] = r3;
            }
#pragma unroll
            for (int mt = 0; mt < 2; mt++)
#pragma unroll
                for (int nt = 0; nt < 8; nt++)
                    mma_bf16(acc[mt][nt], af[mt], bf[nt]);
        }
        __syncthreads();
        if (c + 2 < NC) B_ISSUE(c + 2, buf);
        CP_COMMIT();
        CP_WAIT1();
        __syncthreads();
    }
#undef B_ISSUE

#pragma unroll
    for (int mt = 0; mt < 2; mt++) {
        int row = warp_m * 32 + mt * 16 + (lane >> 2);
        float* c0 = C + (size_t)row * NDE + n0;
        float* c1 = C + (size_t)(row + 8) * NDE + n0;
        const float* wb = Wbase + n0;
#pragma unroll
        for (int nt = 0; nt < 8; nt++) {
            int col = nt * 8 + (lane & 3) * 2;
            float2 w2 = *(const float2*)(wb + col);
            float2 o0, o1;
            o0.x = acc[mt][nt][0] + w2.x; o0.y = acc[mt][nt][1] + w2.y;
            o1.x = acc[mt][nt][2] + w2.x; o1.y = acc[mt][nt][3] + w2.y;
            *(float2*)(c0 + col) = o0;
            *(float2*)(c1 + col) = o1;
        }
    }
}

// ---------------- h_t + residual + LayerNorm (sums b_delta partials) ----------------
__global__ void ht_ln_kernel(const float* __restrict__ Wout, const float* __restrict__ hA,
                             const float* __restrict__ bparts, const float* __restrict__ b_base,
                             const float* __restrict__ gamma_p, const float* __restrict__ ln_s,
                             const float* __restrict__ ln_b, float* __restrict__ hmid)
{
    int b = blockIdx.x, tid = threadIdx.x;     // 256 threads
    int lane = tid & 31, warp = tid >> 5;
    __shared__ float hs[DA];
    __shared__ float ys[DA];
    __shared__ float bsum[DB];
    hs[tid] = hA[(size_t)b * DA + tid];
    {
        float bs = 0.0f;
#pragma unroll
        for (int ks = 0; ks < BDS; ks++)
            bs += bparts[(size_t)ks * BATCH * DB + (size_t)b * DB + tid];
        bsum[tid] = bs;
    }
    __syncthreads();
    float gamma = gamma_p[0];
    const float* Wb = Wout + (size_t)b * NDE;
    for (int c = warp; c < DB; c += 8) {
        const float* row = Wb + (size_t)c * DA;
        float s = 0.0f;
#pragma unroll
        for (int i = 0; i < 8; i++) { int a = lane + 32 * i; s += row[a] * hs[a]; }
#pragma unroll
        for (int o = 16; o; o >>= 1) s += __shfl_xor_sync(0xffffffffu, s, o);
        if (lane == 0) {
            float htv = s + bsum[c] + b_base[c];
            ys[c] = hs[c] + gamma * htv;
        }
    }
    __syncthreads();
    float v = ys[tid];
    float s1 = v, s2 = v * v;
#pragma unroll
    for (int o = 16; o; o >>= 1) {
        s1 += __shfl_xor_sync(0xffffffffu, s1, o);
        s2 += __shfl_xor_sync(0xffffffffu, s2, o);
    }
    __shared__ float red[18];
    if (lane == 0) { red[warp] = s1; red[8 + warp] = s2; }
    __syncthreads();
    if (tid == 0) {
        float a = 0.0f, q = 0.0f;
#pragma unroll
        for (int i = 0; i < 8; i++) { a += red[i]; q += red[8 + i]; }
        red[16] = a / (float)DA;
        red[17] = q / (float)DA;
    }
    __syncthreads();
    float mu = red[16];
    float var = fmaxf(red[17] - mu * mu, 0.0f);
    float r = rsqrtf(var + 1e-6f);
    hmid[(size_t)b * DA + tid] = (v - mu) * r * ln_s[tid] + ln_b[tid];
}

// ---------------- launch ----------------
extern "C" void kernel_launch(void* const* d_in, const int* in_sizes, int n_in,
                              void* d_out, int out_size)
{
    const float* x      = (const float*)d_in[0];
    const float* pool   = (const float*)d_in[1];
    const float* A_w0   = (const float*)d_in[2];
    const float* A_b0   = (const float*)d_in[3];
    const float* A_w1   = (const float*)d_in[4];
    const float* A_b1   = (const float*)d_in[5];
    const float* W_Q    = (const float*)d_in[6];
    const float* W_K    = (const float*)d_in[7];
    const float* logits = (const float*)d_in[8];
    const float* tau    = (const float*)d_in[9];
    const float* W_base = (const float*)d_in[10];
    const float* b_base = (const float*)d_in[11];
    const float* gamma  = (const float*)d_in[12];
    const float* ln_s   = (const float*)d_in[13];
    const float* ln_b   = (const float*)d_in[14];
    const float* B_w0   = (const float*)d_in[15];
    const float* B_b0   = (const float*)d_in[16];
    const float* B_w1   = (const float*)d_in[17];
    const float* B_b1   = (const float*)d_in[18];

    float* out       = (float*)d_out;
    float* out_alpha = out + OUT_ALPHA;
    float* out_W     = out + OUT_W;
    float* out_keys  = out + OUT_KEYS;

    float *p_hid, *p_hA, *p_qw, *p_kn, *p_bt, *p_hmid, *p_hid2, *p_kp;
    __nv_bfloat16 *p_ab, *p_UVb, *p_px, *p_wx;
    cudaGetSymbolAddress((void**)&p_hid,  g_hid);
    cudaGetSymbolAddress((void**)&p_hA,   g_hA);
    cudaGetSymbolAddress((void**)&p_qw,   g_qw);
    cudaGetSymbolAddress((void**)&p_kn,   g_kn);
    cudaGetSymbolAddress((void**)&p_bt,   g_bt);
    cudaGetSymbolAddress((void**)&p_hmid, g_hmid);
    cudaGetSymbolAddress((void**)&p_hid2, g_hid2);
    cudaGetSymbolAddress((void**)&p_kp,   g_kp);
    cudaGetSymbolAddress((void**)&p_ab,   g_alphab);
    cudaGetSymbolAddress((void**)&p_UVb,  g_UVb);
    cudaGetSymbolAddress((void**)&p_px,   g_poolx);
    cudaGetSymbolAddress((void**)&p_wx,   g_wkx);

    cudaFuncSetAttribute(big_mma_kernel, cudaFuncAttributeMaxDynamicSharedMemorySize, B4_SMEM);

    // 1) FUSED prologue: expand_pool + expand_wk + gemm#1
    prologue_kernel<<<2976, 256>>>(pool, p_px, W_K, p_wx, x, A_w0, A_b0, p_hid);
    // 2) FUSED keys split-bf16 mma (1024) + UV build f32x2 (2048)
    keys_uv_kernel<<<3072, 128>>>(p_px, p_wx, p_kp, pool, p_UVb);
    // 3) reduce + keys output + k_norm
    knorm_kernel<<<dim3(NP, SA), 64>>>(p_kp, out_keys, p_kn);
    // 4) h_A MLP second gemm
    gemm64<0><<<dim3(DA / 64, BATCH / 64), 256>>>(p_hid, A_w1, A_b1, p_hA, HIDN, HIDN, DA, DA);
    // 5) queries
    q_kernel<<<dim3(BATCH, SA), 64>>>(p_hA, W_Q, logits, p_qw);
    // 6-7) scores -> alpha
    scores_kernel<<<dim3(NP / 64, BATCH / 64), 256>>>(p_qw, p_kn, tau, out_alpha);
    alpha_norm_kernel<<<BATCH, 256>>>(out_alpha, p_ab);
    // 8) FUSED big GEMM (1024) + bdelta split-K (128)
    big_mma_kernel<<<1152, 256, B4_SMEM>>>(p_ab, p_UVb, W_base, out_W, out_alpha, pool, p_bt);
    // 9) h_t, residual, layernorm
    ht_ln_kernel<<<BATCH, 256>>>(out_W, p_hA, p_bt, b_base, gamma, ln_s, ln_b, p_hmid);
    // 10-11) output MLP
    gemm64<1><<<dim3(HIDN / 64, BATCH / 64), 256>>>(p_hmid, B_w0, B_b0, p_hid2, DA, DA, HIDN, HIDN);
    gemm64<0><<<dim3(DMODEL / 64, BATCH / 64), 256>>>(p_hid2, B_w1, B_b1, out, HIDN, HIDN, DMODEL, DMODEL);
}